// round 15
// baseline (speedup 1.0000x reference)
#include <cuda_runtime.h>
#include <cuda_fp16.h>
#include <math.h>
#include <stdint.h>

#define N_    4096
#define E_    131072
#define FEAT_ 64
#define HID_  256
#define NEG_  (-1e9f)
#define KZ_   4

typedef __half hf;

// ---------------- scratch ----------------
__device__ float g_h0 [N_*HID_];
__device__ float g_x  [N_*HID_];
__device__ float g_hl_[N_*HID_];
__device__ float g_xg [N_*HID_];
__device__ float g_part[(size_t)KZ_*N_*HID_];
__device__ uint32_t g_mb[(size_t)N_*N_/32];
__device__ float g_Mb[N_*32], g_Zb[N_*32], g_Cb[N_*32];
__device__ hf g_xh[N_*HID_], g_xl[N_*HID_];
__device__ hf g_feath[N_*FEAT_], g_featl[N_*FEAT_];
__device__ hf g_suph[N_*2*HID_], g_supl[N_*2*HID_];
__device__ hf g_hmsh[N_*HID_], g_hmsl[N_*HID_];
__device__ hf g_qh[N_*HID_];
__device__ hf g_kh[N_*HID_];
__device__ hf g_vth[HID_*N_];
__device__ hf g_sh[(size_t)N_*N_];
__device__ hf g_fcWth[HID_*FEAT_];
__device__ hf g_gatWth[4*HID_*HID_];
__device__ hf g_gcWth[4*HID_*2*HID_];
__device__ hf g_qkvWth[4*768*HID_];
__device__ float g_qkvb[4*768];
__device__ hf g_oWth[4*HID_*HID_];
__device__ float g_el [N_*4];
__device__ float g_er [N_*4];
__device__ float g_y  [N_];
__device__ float g_xyz0[N_*3];
__device__ float g_xyz1[N_*3];
__device__ float g_xs_[N_], g_ys_[N_], g_zs_[N_];
__device__ int   g_cnt[N_];
__device__ int   g_rowptr[N_+1];
__device__ int   g_cur[N_];
__device__ int   g_psrc[E_];
__device__ int   g_maskmode;

// ---------------- helpers ----------------
__device__ __forceinline__ uint32_t smem_u32(const void* p) {
    uint32_t a;
    asm("{ .reg .u64 t; cvta.to.shared.u64 t, %1; cvt.u32.u64 %0, t; }" : "=r"(a) : "l"(p));
    return a;
}
#define LDMX4(r, a) \
    asm volatile("ldmatrix.sync.aligned.m8n8.x4.shared.b16 {%0,%1,%2,%3}, [%4];" \
        : "=r"((r)[0]), "=r"((r)[1]), "=r"((r)[2]), "=r"((r)[3]) : "r"(a))
#define MMA16816(c, a, b0, b1) \
    asm volatile("mma.sync.aligned.m16n8k16.row.col.f32.f16.f16.f32 " \
        "{%0,%1,%2,%3}, {%4,%5,%6,%7}, {%8,%9}, {%0,%1,%2,%3};" \
        : "+f"((c)[0]), "+f"((c)[1]), "+f"((c)[2]), "+f"((c)[3]) \
        : "r"((a)[0]), "r"((a)[1]), "r"((a)[2]), "r"((a)[3]), "r"(b0), "r"(b1))

__device__ __forceinline__ void split1h(float v, hf& h, hf& l) {
    h = __float2half_rn(v);
    l = __float2half_rn(v - __half2float(h));
}
__device__ __forceinline__ void scale8(uint4& v, float c) {
    half2 cc = __float2half2_rn(c);
    half2* p = (half2*)&v;
    p[0] = __hmul2(p[0], cc); p[1] = __hmul2(p[1], cc);
    p[2] = __hmul2(p[2], cc); p[3] = __hmul2(p[3], cc);
}

__device__ __forceinline__ float fast_exp(float x) {
    float t = x * 1.4426950408889634f;
    t = fmaxf(t, -126.0f);
    float z = t + 12582912.0f;
    float n = z - 12582912.0f;
    float f = t - n;
    float p = 1.5404e-4f;
    p = fmaf(p, f, 1.33336e-3f);
    p = fmaf(p, f, 9.61813e-3f);
    p = fmaf(p, f, 5.550411e-2f);
    p = fmaf(p, f, 2.4022651e-1f);
    p = fmaf(p, f, 6.9314718e-1f);
    p = fmaf(p, f, 1.0f);
    int ni = __float_as_int(z) - 0x4B400000;
    float sc = __int_as_float((ni + 127) << 23);
    return p * sc;
}

__global__ void detect_mask_mode(const unsigned int* __restrict__ m) {
    bool allbin = true, anyfloat = false;
    for (int i = 0; i < 1024; i++) {
        unsigned int w = m[i];
        if (w == 0x3f800000u) anyfloat = true;
        if (w > 1u) allbin = false;
    }
    g_maskmode = anyfloat ? 2 : (allbin ? 1 : 0);
}
__device__ __forceinline__ bool mask_at(const void* p, size_t i, int mode) {
    if (mode == 0) return ((const unsigned char*)p)[i] != 0;
    if (mode == 1) return ((const int*)p)[i] != 0;
    return ((const float*)p)[i] != 0.0f;
}

__global__ void maskpack(const void* __restrict__ dmask, const void* __restrict__ bmask,
                         uint32_t* __restrict__ out)
{
    int w = blockIdx.x * 256 + threadIdx.x;
    const int mode = g_maskmode;
    const size_t base = (size_t)w * 32;
    uint32_t bits = 0;
#pragma unroll 4
    for (int e = 0; e < 32; e++)
        if (mask_at(dmask, base + e, mode) && mask_at(bmask, base + e, mode))
            bits |= (1u << e);
    out[w] = bits;
}

__global__ void split_hf(const float* __restrict__ X, hf* __restrict__ Xh, hf* __restrict__ Xl)
{
    int i = blockIdx.x * blockDim.x + threadIdx.x;
    float4 x = *(const float4*)&X[(size_t)i*4];
    float xv[4] = {x.x, x.y, x.z, x.w};
    __align__(8) hf h[4], l[4];
#pragma unroll
    for (int e = 0; e < 4; e++) split1h(xv[e], h[e], l[e]);
    *(uint2*)&Xh[(size_t)i*4] = *(uint2*)h;
    *(uint2*)&Xl[(size_t)i*4] = *(uint2*)l;
}

__global__ void wsplit(const float* __restrict__ W, hf* __restrict__ Wth,
                       int K, int N, int KN)
{
    int idx = blockIdx.x * 256 + threadIdx.x;
    int mat = idx / KN;
    int rem = idx - mat * KN;
    int k = rem / N;
    int n = rem - k * N;
    Wth[mat * KN + n * K + k] = __float2half_rn(W[idx]);
}

__global__ void wsplit_ro(const float* __restrict__ W, hf* __restrict__ Wth, int ro)
{
    int idx = blockIdx.x * 256 + threadIdx.x;
    int l = idx >> 16;
    int rem = idx & 65535;
    int k = rem >> 8, n = rem & 255;
    Wth[(size_t)l * 768 * HID_ + (size_t)(ro + n) * HID_ + k] = __float2half_rn(W[idx]);
}

__global__ void qkvbias(const float* __restrict__ qb, const float* __restrict__ kb,
                        const float* __restrict__ vb, float* __restrict__ out)
{
    int idx = blockIdx.x * 256 + threadIdx.x;
    if (idx >= 4*768) return;
    int l = idx / 768, c = idx % 768;
    int sect = c >> 8, cc = c & 255;
    out[idx] = (sect == 0) ? qb[l*256+cc] : (sect == 1) ? kb[l*256+cc] : vb[l*256+cc];
}

// ================= gemm_tc64: 64x64 tile fp16-mma, 2-pass (A split, B single) ===========
__global__ __launch_bounds__(256) void gemm_tc64(
    const hf* __restrict__ Ah, const hf* __restrict__ Al,
    const hf* __restrict__ Bh,
    int K, int Nc,
    const float* __restrict__ bias, int relu, float cacc,
    const float* __restrict__ X1, float c1,
    const float* __restrict__ X2, float c2,
    const float* __restrict__ X3, float c3,
    float* __restrict__ C, float* __restrict__ C2,
    hf* __restrict__ Ch, hf* __restrict__ Cl)
{
    __shared__ __align__(16) char Ash[2][64*80];
    __shared__ __align__(16) char Bsh[2][64*80];
    const int t = threadIdx.x, lane = t & 31, wid = t >> 5;
    const int wr32 = (wid >> 2) * 32, wc16 = (wid & 3) * 16;
    const int g = lane >> 2, tg = lane & 3;
    const int a_r = ((lane >> 3) & 1) * 8 + (lane & 7);
    const int a_c = (lane >> 4) * 16;
    const int b_r = ((lane >> 4) & 1) * 8 + (lane & 7);
    const int b_c = ((lane >> 3) & 1) * 16;
    const int m0 = blockIdx.y * 64, n0 = blockIdx.x * 64;
    const int lrow = t >> 2, lq = t & 3;

    uint32_t aS[2] = { smem_u32(Ash[0]), smem_u32(Ash[1]) };
    uint32_t bS[2] = { smem_u32(Bsh[0]), smem_u32(Bsh[1]) };
    float acc[2][2][4] = {};

    const hf* APs[2] = { Ah, Al };
    const int chunks = K >> 5;
    const int NC = 2 * chunks;

    uint4 va = *(const uint4*)(APs[0] + (size_t)(m0+lrow)*K + lq*8);
    uint4 vb = *(const uint4*)(Bh + (size_t)(n0+lrow)*K + lq*8);
    *(uint4*)(Ash[0] + lrow*80 + lq*16) = va;
    *(uint4*)(Bsh[0] + lrow*80 + lq*16) = vb;
    __syncthreads();

    int pn = 0, kn = 0;
    for (int c = 0; c < NC; c++) {
        const int buf = c & 1;
        const bool more = (c + 1 < NC);
        if (more) {
            kn++; if (kn == chunks) { kn = 0; pn++; }
            va = *(const uint4*)(APs[pn] + (size_t)(m0+lrow)*K + kn*32 + lq*8);
            vb = *(const uint4*)(Bh + (size_t)(n0+lrow)*K + kn*32 + lq*8);
        }
#pragma unroll
        for (int kk = 0; kk < 2; kk++) {
            uint32_t af[2][4], bfr[4];
#pragma unroll
            for (int mt = 0; mt < 2; mt++) {
                uint32_t ad = aS[buf] + (uint32_t)((wr32 + mt*16 + a_r)*80 + kk*32 + a_c);
                LDMX4(af[mt], ad);
            }
            {
                uint32_t bd = bS[buf] + (uint32_t)((wc16 + b_r)*80 + kk*32 + b_c);
                LDMX4(bfr, bd);
            }
#pragma unroll
            for (int mt = 0; mt < 2; mt++)
#pragma unroll
                for (int nt = 0; nt < 2; nt++)
                    MMA16816(acc[mt][nt], af[mt], bfr[nt*2], bfr[nt*2+1]);
        }
        if (more) {
            const int nb = buf ^ 1;
            *(uint4*)(Ash[nb] + lrow*80 + lq*16) = va;
            *(uint4*)(Bsh[nb] + lrow*80 + lq*16) = vb;
            __syncthreads();
        }
    }

#pragma unroll
    for (int mt = 0; mt < 2; mt++) {
#pragma unroll
        for (int h = 0; h < 2; h++) {
            const int m = m0 + wr32 + mt*16 + g + 8*h;
            const size_t rb = (size_t)m * Nc;
#pragma unroll
            for (int nt = 0; nt < 2; nt++) {
                const int n = n0 + wc16 + nt*8 + 2*tg;
                float2 r = { acc[mt][nt][h*2], acc[mt][nt][h*2+1] };
                r.x *= cacc; r.y *= cacc;
                if (bias) { r.x += bias[n]; r.y += bias[n+1]; }
                if (X1) { float2 q = *(const float2*)&X1[rb+n];
                          r.x = fmaf(c1,q.x,r.x); r.y = fmaf(c1,q.y,r.y); }
                if (X2) { float2 q = *(const float2*)&X2[rb+n];
                          r.x = fmaf(c2,q.x,r.x); r.y = fmaf(c2,q.y,r.y); }
                if (X3) { float2 q = *(const float2*)&X3[rb+n];
                          r.x = fmaf(c3,q.x,r.x); r.y = fmaf(c3,q.y,r.y); }
                if (relu) { r.x = fmaxf(r.x, 0.f); r.y = fmaxf(r.y, 0.f); }
                if (C)  *(float2*)&C[rb+n]  = r;
                if (C2) *(float2*)&C2[rb+n] = r;
                if (Ch) {
                    __align__(4) hf h2[2], l2[2];
                    split1h(r.x, h2[0], l2[0]); split1h(r.y, h2[1], l2[1]);
                    *(uint32_t*)&Ch[rb+n] = *(uint32_t*)h2;
                    *(uint32_t*)&Cl[rb+n] = *(uint32_t*)l2;
                }
            }
        }
    }
}

// ================= qkv_tc: fused QKV GEMM, tile 128x64, Nc=768 routed =================
__global__ __launch_bounds__(256) void qkv_tc(
    const hf* __restrict__ Ah, const hf* __restrict__ Al,
    const hf* __restrict__ Bh,
    const float* __restrict__ bias,
    hf* __restrict__ Qh, hf* __restrict__ Kh, hf* __restrict__ Vth)
{
    __shared__ __align__(16) char Ash[2][128*80];
    __shared__ __align__(16) char Bsh[2][64*80];
    const int t = threadIdx.x, lane = t & 31, wid = t >> 5;
    const int wr32 = (wid >> 1) * 32, wc32 = (wid & 1) * 32;
    const int g = lane >> 2, tg = lane & 3;
    const int a_r = ((lane >> 3) & 1) * 8 + (lane & 7);
    const int a_c = (lane >> 4) * 16;
    const int b_r = ((lane >> 4) & 1) * 8 + (lane & 7);
    const int b_c = ((lane >> 3) & 1) * 16;
    const int m0 = blockIdx.y * 128, n0 = blockIdx.x * 64;
    const int K = HID_;

    uint32_t aS[2] = { smem_u32(Ash[0]), smem_u32(Ash[1]) };
    uint32_t bS[2] = { smem_u32(Bsh[0]), smem_u32(Bsh[1]) };
    float acc[2][4][4] = {};

    const hf* APs[2] = { Ah, Al };
    const int chunks = K >> 5;
    const int NC = 2 * chunks;

    uint4 va[2], vb;
#pragma unroll
    for (int i = 0; i < 2; i++) {
        int idx = t + i*256, row = idx >> 2, q = idx & 3;
        va[i] = *(const uint4*)(APs[0] + (size_t)(m0+row)*K + q*8);
    }
    { int row = t >> 2, q = t & 3;
      vb = *(const uint4*)(Bh + (size_t)(n0+row)*K + q*8); }
#pragma unroll
    for (int i = 0; i < 2; i++) {
        int idx = t + i*256, row = idx >> 2, q = idx & 3;
        *(uint4*)(Ash[0] + row*80 + q*16) = va[i];
    }
    { int row = t >> 2, q = t & 3;
      *(uint4*)(Bsh[0] + row*80 + q*16) = vb; }
    __syncthreads();

    int pn = 0, kn = 0;
    for (int c = 0; c < NC; c++) {
        const int buf = c & 1;
        const bool more = (c + 1 < NC);
        if (more) {
            kn++; if (kn == chunks) { kn = 0; pn++; }
#pragma unroll
            for (int i = 0; i < 2; i++) {
                int idx = t + i*256, row = idx >> 2, q = idx & 3;
                va[i] = *(const uint4*)(APs[pn] + (size_t)(m0+row)*K + kn*32 + q*8);
            }
            { int row = t >> 2, q = t & 3;
              vb = *(const uint4*)(Bh + (size_t)(n0+row)*K + kn*32 + q*8); }
        }
#pragma unroll
        for (int kk = 0; kk < 2; kk++) {
            uint32_t af[2][4], bfr[2][4];
#pragma unroll
            for (int mt = 0; mt < 2; mt++) {
                uint32_t ad = aS[buf] + (uint32_t)((wr32 + mt*16 + a_r)*80 + kk*32 + a_c);
                LDMX4(af[mt], ad);
            }
#pragma unroll
            for (int np = 0; np < 2; np++) {
                uint32_t bd = bS[buf] + (uint32_t)((wc32 + np*16 + b_r)*80 + kk*32 + b_c);
                LDMX4(bfr[np], bd);
            }
#pragma unroll
            for (int mt = 0; mt < 2; mt++)
#pragma unroll
                for (int nt = 0; nt < 4; nt++)
                    MMA16816(acc[mt][nt], af[mt], bfr[nt>>1][(nt&1)*2], bfr[nt>>1][(nt&1)*2+1]);
        }
        if (more) {
            const int nb = buf ^ 1;
#pragma unroll
            for (int i = 0; i < 2; i++) {
                int idx = t + i*256, row = idx >> 2, q = idx & 3;
                *(uint4*)(Ash[nb] + row*80 + q*16) = va[i];
            }
            { int row = t >> 2, q = t & 3;
              *(uint4*)(Bsh[nb] + row*80 + q*16) = vb; }
            __syncthreads();
        }
    }

#pragma unroll
    for (int mt = 0; mt < 2; mt++) {
#pragma unroll
        for (int h = 0; h < 2; h++) {
            const int m = m0 + wr32 + mt*16 + g + 8*h;
#pragma unroll
            for (int nt = 0; nt < 4; nt++) {
                const int n = n0 + wc32 + nt*8 + 2*tg;
                float2 r = { acc[mt][nt][h*2], acc[mt][nt][h*2+1] };
                r.x += bias[n]; r.y += bias[n+1];
                const int sect = n >> 8, cc = n & 255;
                if (sect == 0) {
                    __align__(4) hf hh[2] = { __float2half_rn(r.x), __float2half_rn(r.y) };
                    *(uint32_t*)&Qh[(size_t)m*HID_ + cc] = *(uint32_t*)hh;
                } else if (sect == 1) {
                    __align__(4) hf hh[2] = { __float2half_rn(r.x), __float2half_rn(r.y) };
                    *(uint32_t*)&Kh[(size_t)m*HID_ + cc] = *(uint32_t*)hh;
                } else {
                    Vth[(size_t)cc * N_ + m]     = __float2half_rn(r.x);
                    Vth[(size_t)(cc+1) * N_ + m] = __float2half_rn(r.y);
                }
            }
        }
    }
}

// ---- shared mma-core macro (128x128 kernels) ----
#define COMPUTE32(abase, bbase)                                                     \
    _Pragma("unroll")                                                               \
    for (int kk = 0; kk < 2; kk++) {                                                \
        uint32_t af[4][4], bfr[2][4];                                               \
        _Pragma("unroll")                                                           \
        for (int mt = 0; mt < 4; mt++) {                                            \
            uint32_t ad = (abase) + (uint32_t)((wr64 + mt*16 + a_r)*80 + kk*32 + a_c); \
            LDMX4(af[mt], ad);                                                      \
        }                                                                           \
        _Pragma("unroll")                                                           \
        for (int np = 0; np < 2; np++) {                                            \
            uint32_t bd = (bbase) + (uint32_t)((wc32 + np*16 + b_r)*80 + kk*32 + b_c); \
            LDMX4(bfr[np], bd);                                                     \
        }                                                                           \
        _Pragma("unroll")                                                           \
        for (int mt = 0; mt < 4; mt++)                                              \
            _Pragma("unroll")                                                       \
            for (int nt = 0; nt < 4; nt++)                                          \
                MMA16816(acc[mt][nt], af[mt], bfr[nt>>1][(nt&1)*2], bfr[nt>>1][(nt&1)*2+1]); \
    }

// ===== scores + block-local softmax: Sh = exp(s - m_b), per-block Mb/Zb =====
__global__ __launch_bounds__(256) void scores_mma(
    const hf* __restrict__ qh, const hf* __restrict__ kh,
    const float* __restrict__ xyz,
    const uint32_t* __restrict__ Mw,
    hf* __restrict__ Sh, float* __restrict__ MbO, float* __restrict__ ZbO)
{
    __shared__ __align__(16) char Ash[2][128*80];
    __shared__ __align__(16) char Bsh[2][128*80];
    __shared__ float gix[128*3], gisq[128], giy[128];
    __shared__ float gjx[128*3], gjsq[128], gjy[128];
    const int t = threadIdx.x, lane = t & 31, wid = t >> 5;
    const int wr64 = (wid >> 2) * 64, wc32 = (wid & 3) * 32;
    const int g = lane >> 2, tg = lane & 3;
    const int wsub = wid & 3;
    const int a_r = ((lane >> 3) & 1) * 8 + (lane & 7);
    const int a_c = (lane >> 4) * 16;
    const int b_r = ((lane >> 4) & 1) * 8 + (lane & 7);
    const int b_c = ((lane >> 3) & 1) * 16;
    const int i0 = blockIdx.y * 128, j0 = blockIdx.x * 128;
    const int lrow = t >> 2, lq = t & 3;

    if (t < 128) {
        float a = xyz[(i0+t)*3+0], b = xyz[(i0+t)*3+1], c = xyz[(i0+t)*3+2];
        gix[t*3+0]=a; gix[t*3+1]=b; gix[t*3+2]=c;
        gisq[t] = fmaf(c,c,fmaf(b,b,a*a));
        giy[t]  = g_y[i0+t];
    } else {
        int u = t - 128;
        float a = xyz[(j0+u)*3+0], b = xyz[(j0+u)*3+1], c = xyz[(j0+u)*3+2];
        gjx[u*3+0]=a; gjx[u*3+1]=b; gjx[u*3+2]=c;
        gjsq[u] = fmaf(c,c,fmaf(b,b,a*a));
        gjy[u]  = g_y[j0+u];
    }

    uint32_t aS[2] = { smem_u32(Ash[0]), smem_u32(Ash[1]) };
    uint32_t bS[2] = { smem_u32(Bsh[0]), smem_u32(Bsh[1]) };
    float acc[4][4][4] = {};

    uint4 va[2], vb[2];
#pragma unroll
    for (int r = 0; r < 2; r++) {
        int row = lrow + r*64;
        va[r] = *(const uint4*)(qh + (size_t)(i0+row)*HID_ + lq*8);
        vb[r] = *(const uint4*)(kh + (size_t)(j0+row)*HID_ + lq*8);
    }
#pragma unroll
    for (int r = 0; r < 2; r++) {
        int row = lrow + r*64;
        *(uint4*)(Ash[0] + row*80 + lq*16) = va[r];
        *(uint4*)(Bsh[0] + row*80 + lq*16) = vb[r];
    }
    __syncthreads();

    const int NC = 8;
    for (int c = 0; c < NC; c++) {
        const int buf = c & 1;
        if (c + 1 < NC) {
            const int kc = c + 1;
#pragma unroll
            for (int r = 0; r < 2; r++) {
                int row = lrow + r*64;
                va[r] = *(const uint4*)(qh + (size_t)(i0+row)*HID_ + kc*32 + lq*8);
                vb[r] = *(const uint4*)(kh + (size_t)(j0+row)*HID_ + kc*32 + lq*8);
            }
        }
        COMPUTE32(aS[buf], bS[buf]);
        if (c + 1 < NC) {
            const int nb = buf ^ 1;
#pragma unroll
            for (int r = 0; r < 2; r++) {
                int row = lrow + r*64;
                *(uint4*)(Ash[nb] + row*80 + lq*16) = va[r];
                *(uint4*)(Bsh[nb] + row*80 + lq*16) = vb[r];
            }
            __syncthreads();
        }
    }

    // ----- epilogue: scores -> block-local softmax -----
    __syncthreads();                       // done with smem buffers
    float* redm = (float*)Ash[0];          // 128*4 floats
    float* redz = (float*)(Ash[0] + 2048); // 128*4 floats

    // phase A: compute s values into acc, per-row-per-warp max
#pragma unroll
    for (int mt = 0; mt < 4; mt++) {
#pragma unroll
        for (int h = 0; h < 2; h++) {
            const int li = wr64 + mt*16 + g + 8*h;
            const int gi = i0 + li;
            const float xa = gix[li*3], xbv = gix[li*3+1], xc = gix[li*3+2];
            const float sqa = gisq[li], ya = giy[li];
            const uint32_t wbits = Mw[(size_t)gi * (N_/32) + ((j0 + wc32) >> 5)];
            float tmax = -1e30f;
#pragma unroll
            for (int nt = 0; nt < 4; nt++) {
#pragma unroll
                for (int e = 0; e < 2; e++) {
                    const int lj = wc32 + nt*8 + 2*tg + e;
                    const int bitpos = nt*8 + 2*tg + e;
                    float dot = fmaf(xc, gjx[lj*3+2], fmaf(xbv, gjx[lj*3+1], xa * gjx[lj*3]));
                    float dist2 = (sqa + gjsq[lj]) - 2.0f * dot;
                    bool ok = ((wbits >> bitpos) & 1u) && (dist2 <= 100.0f);
                    float sc = ok ? (acc[mt][nt][h*2+e] * 0.0625f - fabsf(ya - gjy[lj])) : NEG_;
                    acc[mt][nt][h*2+e] = sc;
                    tmax = fmaxf(tmax, sc);
                }
            }
            tmax = fmaxf(tmax, __shfl_xor_sync(0xffffffffu, tmax, 1));
            tmax = fmaxf(tmax, __shfl_xor_sync(0xffffffffu, tmax, 2));
            if (tg == 0) redm[li*4 + wsub] = tmax;
        }
    }
    __syncthreads();

    // phase B: exp(s - m_b), write Sh, per-row-per-warp sums
#pragma unroll
    for (int mt = 0; mt < 4; mt++) {
#pragma unroll
        for (int h = 0; h < 2; h++) {
            const int li = wr64 + mt*16 + g + 8*h;
            const int gi = i0 + li;
            const float mb = fmaxf(fmaxf(redm[li*4], redm[li*4+1]),
                                   fmaxf(redm[li*4+2], redm[li*4+3]));
            const size_t rb = (size_t)gi * N_;
            float zsum = 0.0f;
#pragma unroll
            for (int nt = 0; nt < 4; nt++) {
                float e0 = fast_exp(acc[mt][nt][h*2]   - mb);
                float e1 = fast_exp(acc[mt][nt][h*2+1] - mb);
                zsum += e0 + e1;
                __align__(4) hf hh[2] = { __float2half_rn(e0), __float2half_rn(e1) };
                *(uint32_t*)&Sh[rb + j0 + wc32 + nt*8 + 2*tg] = *(uint32_t*)hh;
            }
            zsum += __shfl_xor_sync(0xffffffffu, zsum, 1);
            zsum += __shfl_xor_sync(0xffffffffu, zsum, 2);
            if (tg == 0) redz[li*4 + wsub] = zsum;
        }
    }
    __syncthreads();

    // phase C: one writer per row
    if (t < 128) {
        const int li = t, gi = i0 + li;
        float mb = fmaxf(fmaxf(redm[li*4], redm[li*4+1]),
                         fmaxf(redm[li*4+2], redm[li*4+3]));
        float zb = redz[li*4] + redz[li*4+1] + redz[li*4+2] + redz[li*4+3];
        MbO[(size_t)gi*32 + blockIdx.x] = mb;
        ZbO[(size_t)gi*32 + blockIdx.x] = zb;
    }
}

// per-row combine: Cb[row][b] = exp(m_b - M) / Z
__global__ void combine_c(const float* __restrict__ Mb, const float* __restrict__ Zb,
                          float* __restrict__ Cb)
{
    int row = blockIdx.x * 256 + threadIdx.x;
    const float* mr = Mb + (size_t)row * 32;
    const float* zr = Zb + (size_t)row * 32;
    float M = -1e30f;
#pragma unroll 8
    for (int b = 0; b < 32; b++) M = fmaxf(M, mr[b]);
    float Z = 0.0f;
#pragma unroll 8
    for (int b = 0; b < 32; b++) Z += zr[b] * fast_exp(mr[b] - M);
    float inv = 1.0f / Z;
    float* cr = Cb + (size_t)row * 32;
#pragma unroll 8
    for (int b = 0; b < 32; b++) cr[b] = fast_exp(mr[b] - M) * inv;
}

// attn @ xyz from Sh * Cb
__global__ void attn_xyz(const hf* __restrict__ Sh, const float* __restrict__ Cb,
                         const float* __restrict__ xs, const float* __restrict__ ys,
                         const float* __restrict__ zs, float* __restrict__ out)
{
    __shared__ float r0[256], r1[256], r2[256];
    const int row = blockIdx.x, t = threadIdx.x;
    const hf* p = Sh + (size_t)row * N_;
    const float* cbr = Cb + (size_t)row * 32;
    float a0 = 0.f, a1 = 0.f, a2 = 0.f;
#pragma unroll
    for (int c = 0; c < 4; c++) {
        const int j = c*1024 + t*4;
        const float cb = cbr[j >> 7];
        uint2 pk = *(const uint2*)&p[j];
        half2 h01 = *(half2*)&pk.x, h23 = *(half2*)&pk.y;
        float w0 = __low2float(h01)*cb, w1 = __high2float(h01)*cb;
        float w2 = __low2float(h23)*cb, w3 = __high2float(h23)*cb;
        a0 = fmaf(w0, xs[j], fmaf(w1, xs[j+1], fmaf(w2, xs[j+2], fmaf(w3, xs[j+3], a0))));
        a1 = fmaf(w0, ys[j], fmaf(w1, ys[j+1], fmaf(w2, ys[j+2], fmaf(w3, ys[j+3], a1))));
        a2 = fmaf(w0, zs[j], fmaf(w1, zs[j+1], fmaf(w2, zs[j+2], fmaf(w3, zs[j+3], a2))));
    }
    r0[t]=a0; r1[t]=a1; r2[t]=a2; __syncthreads();
    for (int s = 128; s > 0; s >>= 1) {
        if (t < s) { r0[t]+=r0[t+s]; r1[t]+=r1[t+s]; r2[t]+=r2[t+s]; }
        __syncthreads();
    }
    if (t == 0) { out[row*3+0]=r0[0]; out[row*3+1]=r1[0]; out[row*3+2]=r2[0]; }
}

// ================= attn@V via fp16 mma (Sh scaled by Cb on load), split-K z ======
__global__ __launch_bounds__(256) void attnv_mma(
    const hf* __restrict__ Sh,
    const hf* __restrict__ Vth,
    const float* __restrict__ Cb,
    float* __restrict__ Cpart)
{
    __shared__ __align__(16) char Ash[2][128*80];
    __shared__ __align__(16) char Bsh[2][128*80];
    const int t = threadIdx.x, lane = t & 31, wid = t >> 5;
    const int wr64 = (wid >> 2) * 64, wc32 = (wid & 3) * 32;
    const int g = lane >> 2, tg = lane & 3;
    const int a_r = ((lane >> 3) & 1) * 8 + (lane & 7);
    const int a_c = (lane >> 4) * 16;
    const int b_r = ((lane >> 4) & 1) * 8 + (lane & 7);
    const int b_c = ((lane >> 3) & 1) * 16;
    const int m0 = blockIdx.y * 128, n0 = blockIdx.x * 128;
    const int kbase = blockIdx.z * (N_ / KZ_);
    const int lrow = t >> 2, lq = t & 3;

    uint32_t aS[2] = { smem_u32(Ash[0]), smem_u32(Ash[1]) };
    uint32_t bS[2] = { smem_u32(Bsh[0]), smem_u32(Bsh[1]) };
    float acc[4][4][4] = {};

    const int NC = (N_ / KZ_) / 32;

    uint4 va[2], vb[2];
    {
        const int ktile = kbase >> 7;
#pragma unroll
        for (int r = 0; r < 2; r++) {
            int row = lrow + r*64;
            va[r] = *(const uint4*)(Sh + (size_t)(m0+row)*N_ + kbase + lq*8);
            scale8(va[r], Cb[(size_t)(m0+row)*32 + ktile]);
            vb[r] = *(const uint4*)(Vth + (size_t)(n0+row)*N_ + kbase + lq*8);
        }
    }
#pragma unroll
    for (int r = 0; r < 2; r++) {
        int row = lrow + r*64;
        *(uint4*)(Ash[0] + row*80 + lq*16) = va[r];
        *(uint4*)(Bsh[0] + row*80 + lq*16) = vb[r];
    }
    __syncthreads();

    for (int c = 0; c < NC; c++) {
        const int buf = c & 1;
        if (c + 1 < NC) {
            const int kc = c + 1;
            const int ktile = (kbase + kc*32) >> 7;
#pragma unroll
            for (int r = 0; r < 2; r++) {
                int row = lrow + r*64;
                va[r] = *(const uint4*)(Sh + (size_t)(m0+row)*N_ + kbase + kc*32 + lq*8);
                scale8(va[r], Cb[(size_t)(m0+row)*32 + ktile]);
                vb[r] = *(const uint4*)(Vth + (size_t)(n0+row)*N_ + kbase + kc*32 + lq*8);
            }
        }
        COMPUTE32(aS[buf], bS[buf]);
        if (c + 1 < NC) {
            const int nb = buf ^ 1;
#pragma unroll
            for (int r = 0; r < 2; r++) {
                int row = lrow + r*64;
                *(uint4*)(Ash[nb] + row*80 + lq*16) = va[r];
                *(uint4*)(Bsh[nb] + row*80 + lq*16) = vb[r];
            }
            __syncthreads();
        }
    }

    float* Cz = Cpart + (size_t)blockIdx.z * N_ * HID_;
#pragma unroll
    for (int mt = 0; mt < 4; mt++) {
#pragma unroll
        for (int h = 0; h < 2; h++) {
            const int m = m0 + wr64 + mt*16 + g + 8*h;
            const size_t rb = (size_t)m * HID_;
#pragma unroll
            for (int nt = 0; nt < 4; nt++) {
                const int n = n0 + wc32 + nt*8 + 2*tg;
                float2 r = { acc[mt][nt][h*2], acc[mt][nt][h*2 + 1] };
                *(float2*)&Cz[rb + n] = r;
            }
        }
    }
}

__global__ void combine_parts(const float* __restrict__ P,
                              hf* __restrict__ Hh, hf* __restrict__ Hl)
{
    int i = blockIdx.x * blockDim.x + threadIdx.x;
    const size_t n = (size_t)N_ * HID_;
    float4 a = *(const float4*)&P[(size_t)i*4];
    float4 b = *(const float4*)&P[n + (size_t)i*4];
    float4 c = *(const float4*)&P[2*n + (size_t)i*4];
    float4 d = *(const float4*)&P[3*n + (size_t)i*4];
    float rv[4] = { a.x+b.x+c.x+d.x, a.y+b.y+c.y+d.y, a.z+b.z+c.z+d.z, a.w+b.w+c.w+d.w };
    __align__(8) hf hh[4], ll[4];
#pragma unroll
    for (int e = 0; e < 4; e++) split1h(rv[e], hh[e], ll[e]);
    *(uint2*)&Hh[(size_t)i*4] = *(uint2*)hh;
    *(uint2*)&Hl[(size_t)i*4] = *(uint2*)ll;
}

__global__ void xyz2soa(const float* __restrict__ xyz, float* __restrict__ xs,
                        float* __restrict__ ys, float* __restrict__ zs)
{
    int i = blockIdx.x * blockDim.x + threadIdx.x;
    if (i < N_) { xs[i] = xyz[3*i]; ys[i] = xyz[3*i+1]; zs[i] = xyz[3*i+2]; }
}

// ---------------- GAT pieces ----------------
__global__ void compute_elr(const float* __restrict__ hl, const float* __restrict__ al,
                            const float* __restrict__ ar)
{
    int idx = blockIdx.x * blockDim.x + threadIdx.x;
    if (idx >= N_*4) return;
    int node = idx >> 2, h = idx & 3;
    const float* row = hl + (size_t)node * HID_ + h * 64;
    float sl = 0.f, sr = 0.f;
#pragma unroll 8
    for (int d = 0; d < 64; d++) {
        float v = row[d];
        sl = fmaf(v, al[h*64+d], sl);
        sr = fmaf(v, ar[h*64+d], sr);
    }
    g_el[idx] = sl; g_er[idx] = sr;
}

__global__ void zero_cnt() { int i = blockIdx.x*blockDim.x + threadIdx.x; if (i < N_) g_cnt[i] = 0; }
__global__ void count_edges(const int* __restrict__ dst) {
    int e = blockIdx.x*blockDim.x + threadIdx.x; if (e < E_) atomicAdd(&g_cnt[dst[e]], 1);
}
__global__ void scan4096() {
    __shared__ int part[1024];
    int t = threadIdx.x, base = t * 4;
    int a0 = g_cnt[base], a1 = g_cnt[base+1], a2 = g_cnt[base+2], a3 = g_cnt[base+3];
    int s = a0 + a1 + a2 + a3;
    part[t] = s; __syncthreads();
    for (int off = 1; off < 1024; off <<= 1) {
        int v = (t >= off) ? part[t-off] : 0;
        __syncthreads();
        part[t] += v;
        __syncthreads();
    }
    int excl = part[t] - s;
    g_rowptr[base+0] = excl;           g_cur[base+0] = excl;
    g_rowptr[base+1] = excl+a0;        g_cur[base+1] = excl+a0;
    g_rowptr[base+2] = excl+a0+a1;     g_cur[base+2] = excl+a0+a1;
    g_rowptr[base+3] = excl+a0+a1+a2;  g_cur[base+3] = excl+a0+a1+a2;
    if (t == 1023) g_rowptr[4096] = part[1023];
}
__global__ void scatter_edges(const int* __restrict__ src, const int* __restrict__ dst) {
    int e = blockIdx.x*blockDim.x + threadIdx.x;
    if (e < E_) { int p = atomicAdd(&g_cur[dst[e]], 1); g_psrc[p] = src[e]; }
}

__global__ void gat_aggregate(const float* __restrict__ hl, float* __restrict__ xg)
{
    const int node = (blockIdx.x * blockDim.x + threadIdx.x) >> 5;
    const int lane = threadIdx.x & 31;
    if (node >= N_) return;
    const int beg = g_rowptr[node], end = g_rowptr[node+1];
    const float er_i = (lane < 4) ? g_er[node*4 + lane] : 0.f;
    float m = -1e30f;
    for (int p = beg; p < end; p++) {
        int s = g_psrc[p];
        if (lane < 4) {
            float v = g_el[s*4 + lane] + er_i;
            float e = (v > 0.f) ? v : 0.2f * v;
            m = fmaxf(m, e);
        }
    }
    float m0 = __shfl_sync(0xffffffffu, m, 0), m1 = __shfl_sync(0xffffffffu, m, 1);
    float m2 = __shfl_sync(0xffffffffu, m, 2), m3 = __shfl_sync(0xffffffffu, m, 3);
    const int myh = lane >> 3;
    float4 acc0 = {0,0,0,0}, acc1 = {0,0,0,0};
    float z = 0.f;
    for (int p = beg; p < end; p++) {
        int s = g_psrc[p];
        float w = 0.f;
        if (lane < 4) {
            float v = g_el[s*4 + lane] + er_i;
            float e = (v > 0.f) ? v : 0.2f * v;
            float mm = (lane==0)?m0:(lane==1)?m1:(lane==2)?m2:m3;
            w = fast_exp(e - mm);
            z += w;
        }
        float w0 = __shfl_sync(0xffffffffu, w, 0), w1 = __shfl_sync(0xffffffffu, w, 1);
        float w2 = __shfl_sync(0xffffffffu, w, 2), w3 = __shfl_sync(0xffffffffu, w, 3);
        float wm = (myh==0)?w0:(myh==1)?w1:(myh==2)?w2:w3;
        const float4* hp = (const float4*)(hl + (size_t)s * HID_ + lane * 8);
        float4 hv0 = hp[0], hv1 = hp[1];
        acc0.x=fmaf(wm,hv0.x,acc0.x); acc0.y=fmaf(wm,hv0.y,acc0.y);
        acc0.z=fmaf(wm,hv0.z,acc0.z); acc0.w=fmaf(wm,hv0.w,acc0.w);
        acc1.x=fmaf(wm,hv1.x,acc1.x); acc1.y=fmaf(wm,hv1.y,acc1.y);
        acc1.z=fmaf(wm,hv1.z,acc1.z); acc1.w=fmaf(wm,hv1.w,acc1.w);
    }
    float z0 = __shfl_sync(0xffffffffu, z, 0), z1 = __shfl_sync(0xffffffffu, z, 1);
    float z2 = __shfl_sync(0xffffffffu, z, 2), z3 = __shfl_sync(0xffffffffu, z, 3);
    float zm = (myh==0)?z0:(myh==1)?z1:(myh==2)?z2:z3;
    float inv = 1.0f / (zm + 1e-9f);
    acc0.x*=inv; acc0.y*=inv; acc0.z*=inv; acc0.w*=inv;
    acc1.x*=inv; acc1.y*=inv; acc1.z*=inv; acc1.w*=inv;
    float4* op = (float4*)(xg + (size_t)node * HID_ + lane * 8);
    op[0] = acc0; op[1] = acc1;
}

__global__ void pack_support(const float* __restrict__ xg, const float* __restrict__ h0,
                             hf* __restrict__ suph, hf* __restrict__ supl)
{
    int i = blockIdx.x * blockDim.x + threadIdx.x;
    if (i >= N_ * 512) return;
    int r = i >> 9, c = i & 511;
    float v = (c < 256) ? xg[(size_t)r*256 + c] : h0[(size_t)r*256 + (c-256)];
    hf h, l; split1h(v, h, l);
    suph[i] = h; supl[i] = l;
}

__global__ void yhat_k(const float* __restrict__ x, const float* __restrict__ W,
                       const float* __restrict__ b)
{
    int i = blockIdx.x * blockDim.x + threadIdx.x;
    if (i >= N_) return;
    const float* r = x + (size_t)i * HID_;
    float l0 = b[0], l1 = b[1];
#pragma unroll 8
    for (int d = 0; d < HID_; d++) {
        float v = r[d];
        l0 = fmaf(v, W[2*d+0], l0);
        l1 = fmaf(v, W[2*d+1], l1);
    }
    g_y[i] = 1.0f / (1.0f + expf(l0 - l1));
}

__global__ void cls_k(const float* __restrict__ x, const float* __restrict__ W,
                      const float* __restrict__ b, float* __restrict__ out)
{
    int i = blockIdx.x * blockDim.x + threadIdx.x;
    if (i >= N_) return;
    const float* r = x + (size_t)i * HID_;
    float l0 = b[0], l1 = b[1];
#pragma unroll 8
    for (int d = 0; d < HID_; d++) {
        float v = r[d];
        l0 = fmaf(v, W[2*d+0], l0);
        l1 = fmaf(v, W[2*d+1], l1);
    }
    out[2*i+0] = l0;
    out[2*i+1] = l1;
}

// ---------------- host orchestration ----------------
extern "C" void kernel_launch(void* const* d_in, const int* in_sizes, int n_in,
                              void* d_out, int out_size)
{
    const float* feat   = (const float*)d_in[0];
    const float* xyz_in = (const float*)d_in[1];
    const int*   src    = (const int*)  d_in[2];
    const int*   dst    = (const int*)  d_in[3];
    const void*  dmask  = d_in[4];
    const void*  bmask  = d_in[5];
    const float* fcW  = (const float*)d_in[6];
    const float* fcb  = (const float*)d_in[7];
    const float* gatW = (const float*)d_in[8];
    const float* al   = (const float*)d_in[9];
    const float* ar   = (const float*)d_in[10];
    const float* gcW  = (const float*)d_in[11];
    const float* cgW  = (const float*)d_in[12];
    const float* cgb  = (const float*)d_in[13];
    const float* qW   = (const float*)d_in[14];
    const float* qb_  = (const float*)d_in[15];
    const float* kW   = (const float*)d_in[16];
    const float* kb_  = (const float*)d_in[17];
    const float* vW   = (const float*)d_in[18];
    const float* vb_  = (const float*)d_in[19];
    const float* oW   = (const float*)d_in[20];
    const float* ob   = (const float*)d_in[21];
    const float* clsW = (const float*)d_in[22];
    const float* clsb = (const float*)d_in[23];

    float *px, *ph0, *phl, *pxg, *pxyz0, *pxyz1, *pxs, *pys, *pzs, *ppart, *pqkvb;
    float *pMb, *pZb, *pCb;
    uint32_t *pmb;
    hf *pxh, *pxl, *pfeath, *pfeatl, *psuph, *psupl, *phmsh, *phmsl;
    hf *pqh, *pkh, *pvth, *psh;
    hf *pfcWth, *pgatWth, *pgcWth, *pqkvWth, *poWth;
    cudaGetSymbolAddress((void**)&px,    g_x);
    cudaGetSymbolAddress((void**)&ph0,   g_h0);
    cudaGetSymbolAddress((void**)&phl,   g_hl_);
    cudaGetSymbolAddress((void**)&pxg,   g_xg);
    cudaGetSymbolAddress((void**)&pmb,   g_mb);
    cudaGetSymbolAddress((void**)&pMb,   g_Mb);
    cudaGetSymbolAddress((void**)&pZb,   g_Zb);
    cudaGetSymbolAddress((void**)&pCb,   g_Cb);
    cudaGetSymbolAddress((void**)&pxyz0, g_xyz0);
    cudaGetSymbolAddress((void**)&pxyz1, g_xyz1);
    cudaGetSymbolAddress((void**)&pxs,   g_xs_);
    cudaGetSymbolAddress((void**)&pys,   g_ys_);
    cudaGetSymbolAddress((void**)&pzs,   g_zs_);
    cudaGetSymbolAddress((void**)&ppart, g_part);
    cudaGetSymbolAddress((void**)&pqkvb, g_qkvb);
    cudaGetSymbolAddress((void**)&pxh,   g_xh);
    cudaGetSymbolAddress((void**)&pxl,   g_xl);
    cudaGetSymbolAddress((void**)&pfeath,g_feath);
    cudaGetSymbolAddress((void**)&pfeatl,g_featl);
    cudaGetSymbolAddress((void**)&psuph, g_suph);
    cudaGetSymbolAddress((void**)&psupl, g_supl);
    cudaGetSymbolAddress((void**)&phmsh, g_hmsh);
    cudaGetSymbolAddress((void**)&phmsl, g_hmsl);
    cudaGetSymbolAddress((void**)&pqh,   g_qh);
    cudaGetSymbolAddress((void**)&pkh,   g_kh);
    cudaGetSymbolAddress((void**)&pvth,  g_vth);
    cudaGetSymbolAddress((void**)&psh,   g_sh);
    cudaGetSymbolAddress((void**)&pfcWth,  g_fcWth);
    cudaGetSymbolAddress((void**)&pgatWth, g_gatWth);
    cudaGetSymbolAddress((void**)&pgcWth,  g_gcWth);
    cudaGetSymbolAddress((void**)&pqkvWth, g_qkvWth);
    cudaGetSymbolAddress((void**)&poWth,   g_oWth);

    detect_mask_mode<<<1, 1>>>((const unsigned int*)dmask);
    maskpack<<<(N_*(N_/32))/256, 256>>>(dmask, bmask, pmb);

    wsplit<<<(FEAT_*HID_)/256, 256>>>(fcW, pfcWth, FEAT_, HID_, FEAT_*HID_);
    wsplit<<<(4*HID_*HID_)/256, 256>>>(gatW, pgatWth, HID_, HID_, HID_*HID_);
    wsplit<<<(4*2*HID_*HID_)/256, 256>>>(gcW, pgcWth, 2*HID_, HID_, 2*HID_*HID_);
    wsplit<<<(4*HID_*HID_)/256, 256>>>(oW, poWth, HID_, HID_, HID_*HID_);
    wsplit_ro<<<(4*HID_*HID_)/256, 256>>>(qW, pqkvWth, 0);
    wsplit_ro<<<(4*HID_*HID_)/256, 256>>>(kW, pqkvWth, 256);
    wsplit_ro<<<(4*HID_*HID_)/256, 256>>>(vW, pqkvWth, 512);
    qkvbias<<<12, 256>>>(qb_, kb_, vb_, pqkvb);
    split_hf<<<(N_*FEAT_/4)/256, 256>>>(feat, pfeath, pfeatl);

    gemm_tc64<<<dim3(HID_/64, N_/64), 256>>>(pfeath, pfeatl, pfcWth, FEAT_, HID_,
                                             fcb, 1, 1.0f, nullptr,0.f, nullptr,0.f, nullptr,0.f,
                                             px, ph0, pxh, pxl);

    zero_cnt<<<N_/256, 256>>>();
    count_edges<<<E_/256, 256>>>(dst);
    scan4096<<<1, 1024>>>();
    scatter_edges<<<E_/256, 256>>>(src, dst);

    const float ALPHA = 0.1f, LAMDA = 0.5f;
    for (int l = 0; l < 4; l++) {
        gemm_tc64<<<dim3(HID_/64, N_/64), 256>>>(pxh, pxl, pgatWth + (size_t)l*HID_*HID_,
                                                 HID_, HID_,
                                                 nullptr, 0, 1.0f, nullptr,0.f, nullptr,0.f, nullptr,0.f,
                                                 phl, nullptr, nullptr, nullptr);
        compute_elr<<<(N_*4)/256, 256>>>(phl, al + l*4*64, ar + l*4*64);
        gat_aggregate<<<N_/8, 256>>>(phl, pxg);
        pack_support<<<(N_*512)/256, 256>>>(pxg, ph0, psuph, psupl);
        float theta = fminf(1.0f, logf(LAMDA / (float)(l + 1) + 1.0f));
        gemm_tc64<<<dim3(HID_/64, N_/64), 256>>>(psuph, psupl, pgcWth + (size_t)l*2*HID_*HID_,
                                                 2*HID_, HID_,
                                                 nullptr, 0, theta,
                                                 pxg, (1.0f-theta)*(1.0f-ALPHA),
                                                 ph0, (1.0f-theta)*ALPHA,
                                                 px,  1.0f,
                                                 px, nullptr, pxh, pxl);
    }

    yhat_k<<<N_/256, 256>>>(px, cgW, cgb);

    const float* xyz_cur = xyz_in;
    float* xyz_buf[2] = { pxyz0, pxyz1 };
    for (int l = 0; l < 4; l++) {
        qkv_tc<<<dim3(768/64, N_/128), 256>>>(pxh, pxl,
                                              pqkvWth + (size_t)l*768*HID_,
                                              pqkvb + l*768,
                                              pqh, pkh, pvth);
        scores_mma<<<dim3(N_/128, N_/128), 256>>>(pqh, pkh, xyz_cur, pmb, psh, pMb, pZb);
        combine_c<<<N_/256, 256>>>(pMb, pZb, pCb);
        xyz2soa<<<N_/256, 256>>>(xyz_cur, pxs, pys, pzs);
        attn_xyz<<<N_, 256>>>(psh, pCb, pxs, pys, pzs, xyz_buf[l & 1]);
        attnv_mma<<<dim3(HID_/128, N_/128, KZ_), 256>>>(psh, pvth, pCb, ppart);
        combine_parts<<<(N_*HID_/4)/256, 256>>>(ppart, phmsh, phmsl);
        gemm_tc64<<<dim3(HID_/64, N_/64), 256>>>(phmsh, phmsl, poWth + (size_t)l*HID_*HID_,
                                                 HID_, HID_,
                                                 ob + l*HID_, 0, 1.0f,
                                                 px, 1.0f, nullptr,0.f, nullptr,0.f,
                                                 px, nullptr, pxh, pxl);
        xyz_cur = xyz_buf[l & 1];
    }

    cls_k<<<N_/256, 256>>>(px, clsW, clsb, (float*)d_out);
}

// round 16
// speedup vs baseline: 1.1199x; 1.1199x over previous
#include <cuda_runtime.h>
#include <cuda_fp16.h>
#include <math.h>
#include <stdint.h>

#define N_    4096
#define E_    131072
#define FEAT_ 64
#define HID_  256
#define NEG_  (-1e9f)
#define KZ_   4

typedef __half hf;

// ---------------- scratch ----------------
__device__ float g_h0 [N_*HID_];
__device__ float g_x  [N_*HID_];
__device__ float g_hl_[N_*HID_];
__device__ float g_xg [N_*HID_];
__device__ float g_part[(size_t)KZ_*N_*HID_];
__device__ float g_S  [(size_t)N_*N_];
__device__ uint32_t g_mb[(size_t)N_*N_/32];
__device__ hf g_xh[N_*HID_], g_xl[N_*HID_];
__device__ hf g_feath[N_*FEAT_], g_featl[N_*FEAT_];
__device__ hf g_suph[N_*2*HID_], g_supl[N_*2*HID_];
__device__ hf g_hmsh[N_*HID_], g_hmsl[N_*HID_];
__device__ hf g_qh[N_*HID_];
__device__ hf g_kh[N_*HID_];
__device__ hf g_vth[HID_*N_];
__device__ hf g_sh[(size_t)N_*N_];
__device__ hf g_fcWth[HID_*FEAT_];
__device__ hf g_gatWth[4*HID_*HID_];
__device__ hf g_gcWth[4*HID_*2*HID_];
__device__ hf g_qkvWth[4*768*HID_];
__device__ float g_qkvb[4*768];
__device__ hf g_oWth[4*HID_*HID_];
__device__ float g_el [N_*4];
__device__ float g_er [N_*4];
__device__ float g_y  [N_];
__device__ float g_xyz0[N_*3];
__device__ float g_xyz1[N_*3];
__device__ float g_xs_[N_], g_ys_[N_], g_zs_[N_];
__device__ int   g_cnt[N_];
__device__ int   g_rowptr[N_+1];
__device__ int   g_cur[N_];
__device__ int   g_psrc[E_];
__device__ int   g_maskmode;

// ---------------- helpers ----------------
__device__ __forceinline__ uint32_t smem_u32(const void* p) {
    uint32_t a;
    asm("{ .reg .u64 t; cvta.to.shared.u64 t, %1; cvt.u32.u64 %0, t; }" : "=r"(a) : "l"(p));
    return a;
}
#define LDMX4(r, a) \
    asm volatile("ldmatrix.sync.aligned.m8n8.x4.shared.b16 {%0,%1,%2,%3}, [%4];" \
        : "=r"((r)[0]), "=r"((r)[1]), "=r"((r)[2]), "=r"((r)[3]) : "r"(a))
#define MMA16816(c, a, b0, b1) \
    asm volatile("mma.sync.aligned.m16n8k16.row.col.f32.f16.f16.f32 " \
        "{%0,%1,%2,%3}, {%4,%5,%6,%7}, {%8,%9}, {%0,%1,%2,%3};" \
        : "+f"((c)[0]), "+f"((c)[1]), "+f"((c)[2]), "+f"((c)[3]) \
        : "r"((a)[0]), "r"((a)[1]), "r"((a)[2]), "r"((a)[3]), "r"(b0), "r"(b1))

__device__ __forceinline__ void split1h(float v, hf& h, hf& l) {
    h = __float2half_rn(v);
    l = __float2half_rn(v - __half2float(h));
}

__device__ __forceinline__ float fast_exp(float x) {
    float t = x * 1.4426950408889634f;
    t = fmaxf(t, -126.0f);
    float z = t + 12582912.0f;
    float n = z - 12582912.0f;
    float f = t - n;
    float p = 1.5404e-4f;
    p = fmaf(p, f, 1.33336e-3f);
    p = fmaf(p, f, 9.61813e-3f);
    p = fmaf(p, f, 5.550411e-2f);
    p = fmaf(p, f, 2.4022651e-1f);
    p = fmaf(p, f, 6.9314718e-1f);
    p = fmaf(p, f, 1.0f);
    int ni = __float_as_int(z) - 0x4B400000;
    float sc = __int_as_float((ni + 127) << 23);
    return p * sc;
}

__global__ void detect_mask_mode(const unsigned int* __restrict__ m) {
    bool allbin = true, anyfloat = false;
    for (int i = 0; i < 1024; i++) {
        unsigned int w = m[i];
        if (w == 0x3f800000u) anyfloat = true;
        if (w > 1u) allbin = false;
    }
    g_maskmode = anyfloat ? 2 : (allbin ? 1 : 0);
}
__device__ __forceinline__ bool mask_at(const void* p, size_t i, int mode) {
    if (mode == 0) return ((const unsigned char*)p)[i] != 0;
    if (mode == 1) return ((const int*)p)[i] != 0;
    return ((const float*)p)[i] != 0.0f;
}

// pack combined mask into bits (one word = 32 consecutive j for fixed i); vectorized byte path
__global__ void maskpack(const void* __restrict__ dmask, const void* __restrict__ bmask,
                         uint32_t* __restrict__ out)
{
    int w = blockIdx.x * 256 + threadIdx.x;
    const int mode = g_maskmode;
    uint32_t bits = 0;
    if (mode == 0) {
        const uint4* d4 = (const uint4*)((const char*)dmask + (size_t)w * 32);
        const uint4* b4 = (const uint4*)((const char*)bmask + (size_t)w * 32);
        uint4 d0 = d4[0], d1 = d4[1], b0 = b4[0], b1 = b4[1];
        uint32_t dw[8] = {d0.x, d0.y, d0.z, d0.w, d1.x, d1.y, d1.z, d1.w};
        uint32_t bw[8] = {b0.x, b0.y, b0.z, b0.w, b1.x, b1.y, b1.z, b1.w};
#pragma unroll
        for (int q = 0; q < 8; q++)
#pragma unroll
            for (int e = 0; e < 4; e++)
                if (((dw[q] >> (8*e)) & 0xFFu) && ((bw[q] >> (8*e)) & 0xFFu))
                    bits |= 1u << (q*4 + e);
    } else {
        const size_t base = (size_t)w * 32;
#pragma unroll 4
        for (int e = 0; e < 32; e++)
            if (mask_at(dmask, base + e, mode) && mask_at(bmask, base + e, mode))
                bits |= (1u << e);
    }
    out[w] = bits;
}

__global__ void split_hf(const float* __restrict__ X, hf* __restrict__ Xh, hf* __restrict__ Xl)
{
    int i = blockIdx.x * blockDim.x + threadIdx.x;
    float4 x = *(const float4*)&X[(size_t)i*4];
    float xv[4] = {x.x, x.y, x.z, x.w};
    __align__(8) hf h[4], l[4];
#pragma unroll
    for (int e = 0; e < 4; e++) split1h(xv[e], h[e], l[e]);
    *(uint2*)&Xh[(size_t)i*4] = *(uint2*)h;
    *(uint2*)&Xl[(size_t)i*4] = *(uint2*)l;
}

// tiled transpose-convert: W [nmat][K,N] fp32 -> Wt [nmat][N,K] fp16 (coalesced both ways)
__global__ void wsplit_t(const float* __restrict__ W, hf* __restrict__ Wth, int K, int N)
{
    __shared__ hf tile[32][33];
    const int mat = blockIdx.z;
    const int k0 = blockIdx.y * 32, n0 = blockIdx.x * 32;
    const int tx = threadIdx.x & 31, ty = threadIdx.x >> 5;   // 256 thr: ty 0..7
#pragma unroll
    for (int r = ty; r < 32; r += 8)
        tile[r][tx] = __float2half_rn(W[((size_t)mat * K + k0 + r) * N + n0 + tx]);
    __syncthreads();
#pragma unroll
    for (int r = ty; r < 32; r += 8)
        Wth[((size_t)mat * N + n0 + r) * K + k0 + tx] = tile[tx][r];
}

// same, into the combined qkv layout [l][768][256] at row offset ro
__global__ void wsplit_ro_t(const float* __restrict__ W, hf* __restrict__ Wth, int ro)
{
    __shared__ hf tile[32][33];
    const int l = blockIdx.z;
    const int k0 = blockIdx.y * 32, n0 = blockIdx.x * 32;
    const int tx = threadIdx.x & 31, ty = threadIdx.x >> 5;
#pragma unroll
    for (int r = ty; r < 32; r += 8)
        tile[r][tx] = __float2half_rn(W[((size_t)l * 256 + k0 + r) * 256 + n0 + tx]);
    __syncthreads();
#pragma unroll
    for (int r = ty; r < 32; r += 8)
        Wth[((size_t)l * 768 + ro + n0 + r) * 256 + k0 + tx] = tile[tx][r];
}

__global__ void qkvbias(const float* __restrict__ qb, const float* __restrict__ kb,
                        const float* __restrict__ vb, float* __restrict__ out)
{
    int idx = blockIdx.x * 256 + threadIdx.x;
    if (idx >= 4*768) return;
    int l = idx / 768, c = idx % 768;
    int sect = c >> 8, cc = c & 255;
    out[idx] = (sect == 0) ? qb[l*256+cc] : (sect == 1) ? kb[l*256+cc] : vb[l*256+cc];
}

// ================= gemm_tc64: 64x64 tile fp16-mma, 2-pass (A split, B single) ===========
__global__ __launch_bounds__(256) void gemm_tc64(
    const hf* __restrict__ Ah, const hf* __restrict__ Al,
    const hf* __restrict__ Bh,
    int K, int Nc,
    const float* __restrict__ bias, int relu, float cacc,
    const float* __restrict__ X1, float c1,
    const float* __restrict__ X2, float c2,
    const float* __restrict__ X3, float c3,
    float* __restrict__ C, float* __restrict__ C2,
    hf* __restrict__ Ch, hf* __restrict__ Cl)
{
    __shared__ __align__(16) char Ash[2][64*80];
    __shared__ __align__(16) char Bsh[2][64*80];
    const int t = threadIdx.x, lane = t & 31, wid = t >> 5;
    const int wr32 = (wid >> 2) * 32, wc16 = (wid & 3) * 16;
    const int g = lane >> 2, tg = lane & 3;
    const int a_r = ((lane >> 3) & 1) * 8 + (lane & 7);
    const int a_c = (lane >> 4) * 16;
    const int b_r = ((lane >> 4) & 1) * 8 + (lane & 7);
    const int b_c = ((lane >> 3) & 1) * 16;
    const int m0 = blockIdx.y * 64, n0 = blockIdx.x * 64;
    const int lrow = t >> 2, lq = t & 3;

    uint32_t aS[2] = { smem_u32(Ash[0]), smem_u32(Ash[1]) };
    uint32_t bS[2] = { smem_u32(Bsh[0]), smem_u32(Bsh[1]) };
    float acc[2][2][4] = {};

    const hf* APs[2] = { Ah, Al };
    const int chunks = K >> 5;
    const int NC = 2 * chunks;

    uint4 va = *(const uint4*)(APs[0] + (size_t)(m0+lrow)*K + lq*8);
    uint4 vb = *(const uint4*)(Bh + (size_t)(n0+lrow)*K + lq*8);
    *(uint4*)(Ash[0] + lrow*80 + lq*16) = va;
    *(uint4*)(Bsh[0] + lrow*80 + lq*16) = vb;
    __syncthreads();

    int pn = 0, kn = 0;
    for (int c = 0; c < NC; c++) {
        const int buf = c & 1;
        const bool more = (c + 1 < NC);
        if (more) {
            kn++; if (kn == chunks) { kn = 0; pn++; }
            va = *(const uint4*)(APs[pn] + (size_t)(m0+lrow)*K + kn*32 + lq*8);
            vb = *(const uint4*)(Bh + (size_t)(n0+lrow)*K + kn*32 + lq*8);
        }
#pragma unroll
        for (int kk = 0; kk < 2; kk++) {
            uint32_t af[2][4], bfr[4];
#pragma unroll
            for (int mt = 0; mt < 2; mt++) {
                uint32_t ad = aS[buf] + (uint32_t)((wr32 + mt*16 + a_r)*80 + kk*32 + a_c);
                LDMX4(af[mt], ad);
            }
            {
                uint32_t bd = bS[buf] + (uint32_t)((wc16 + b_r)*80 + kk*32 + b_c);
                LDMX4(bfr, bd);
            }
#pragma unroll
            for (int mt = 0; mt < 2; mt++)
#pragma unroll
                for (int nt = 0; nt < 2; nt++)
                    MMA16816(acc[mt][nt], af[mt], bfr[nt*2], bfr[nt*2+1]);
        }
        if (more) {
            const int nb = buf ^ 1;
            *(uint4*)(Ash[nb] + lrow*80 + lq*16) = va;
            *(uint4*)(Bsh[nb] + lrow*80 + lq*16) = vb;
            __syncthreads();
        }
    }

#pragma unroll
    for (int mt = 0; mt < 2; mt++) {
#pragma unroll
        for (int h = 0; h < 2; h++) {
            const int m = m0 + wr32 + mt*16 + g + 8*h;
            const size_t rb = (size_t)m * Nc;
#pragma unroll
            for (int nt = 0; nt < 2; nt++) {
                const int n = n0 + wc16 + nt*8 + 2*tg;
                float2 r = { acc[mt][nt][h*2], acc[mt][nt][h*2+1] };
                r.x *= cacc; r.y *= cacc;
                if (bias) { r.x += bias[n]; r.y += bias[n+1]; }
                if (X1) { float2 q = *(const float2*)&X1[rb+n];
                          r.x = fmaf(c1,q.x,r.x); r.y = fmaf(c1,q.y,r.y); }
                if (X2) { float2 q = *(const float2*)&X2[rb+n];
                          r.x = fmaf(c2,q.x,r.x); r.y = fmaf(c2,q.y,r.y); }
                if (X3) { float2 q = *(const float2*)&X3[rb+n];
                          r.x = fmaf(c3,q.x,r.x); r.y = fmaf(c3,q.y,r.y); }
                if (relu) { r.x = fmaxf(r.x, 0.f); r.y = fmaxf(r.y, 0.f); }
                if (C)  *(float2*)&C[rb+n]  = r;
                if (C2) *(float2*)&C2[rb+n] = r;
                if (Ch) {
                    __align__(4) hf h2[2], l2[2];
                    split1h(r.x, h2[0], l2[0]); split1h(r.y, h2[1], l2[1]);
                    *(uint32_t*)&Ch[rb+n] = *(uint32_t*)h2;
                    *(uint32_t*)&Cl[rb+n] = *(uint32_t*)l2;
                }
            }
        }
    }
}

// ================= qkv_tc: fused QKV GEMM, tile 128x64, Nc=768 routed =================
__global__ __launch_bounds__(256) void qkv_tc(
    const hf* __restrict__ Ah, const hf* __restrict__ Al,
    const hf* __restrict__ Bh,
    const float* __restrict__ bias,
    hf* __restrict__ Qh, hf* __restrict__ Kh, hf* __restrict__ Vth)
{
    __shared__ __align__(16) char Ash[2][128*80];
    __shared__ __align__(16) char Bsh[2][64*80];
    const int t = threadIdx.x, lane = t & 31, wid = t >> 5;
    const int wr32 = (wid >> 1) * 32, wc32 = (wid & 1) * 32;
    const int g = lane >> 2, tg = lane & 3;
    const int a_r = ((lane >> 3) & 1) * 8 + (lane & 7);
    const int a_c = (lane >> 4) * 16;
    const int b_r = ((lane >> 4) & 1) * 8 + (lane & 7);
    const int b_c = ((lane >> 3) & 1) * 16;
    const int m0 = blockIdx.y * 128, n0 = blockIdx.x * 64;
    const int K = HID_;

    uint32_t aS[2] = { smem_u32(Ash[0]), smem_u32(Ash[1]) };
    uint32_t bS[2] = { smem_u32(Bsh[0]), smem_u32(Bsh[1]) };
    float acc[2][4][4] = {};

    const hf* APs[2] = { Ah, Al };
    const int chunks = K >> 5;
    const int NC = 2 * chunks;

    uint4 va[2], vb;
#pragma unroll
    for (int i = 0; i < 2; i++) {
        int idx = t + i*256, row = idx >> 2, q = idx & 3;
        va[i] = *(const uint4*)(APs[0] + (size_t)(m0+row)*K + q*8);
    }
    { int row = t >> 2, q = t & 3;
      vb = *(const uint4*)(Bh + (size_t)(n0+row)*K + q*8); }
#pragma unroll
    for (int i = 0; i < 2; i++) {
        int idx = t + i*256, row = idx >> 2, q = idx & 3;
        *(uint4*)(Ash[0] + row*80 + q*16) = va[i];
    }
    { int row = t >> 2, q = t & 3;
      *(uint4*)(Bsh[0] + row*80 + q*16) = vb; }
    __syncthreads();

    int pn = 0, kn = 0;
    for (int c = 0; c < NC; c++) {
        const int buf = c & 1;
        const bool more = (c + 1 < NC);
        if (more) {
            kn++; if (kn == chunks) { kn = 0; pn++; }
#pragma unroll
            for (int i = 0; i < 2; i++) {
                int idx = t + i*256, row = idx >> 2, q = idx & 3;
                va[i] = *(const uint4*)(APs[pn] + (size_t)(m0+row)*K + kn*32 + q*8);
            }
            { int row = t >> 2, q = t & 3;
              vb = *(const uint4*)(Bh + (size_t)(n0+row)*K + kn*32 + q*8); }
        }
#pragma unroll
        for (int kk = 0; kk < 2; kk++) {
            uint32_t af[2][4], bfr[2][4];
#pragma unroll
            for (int mt = 0; mt < 2; mt++) {
                uint32_t ad = aS[buf] + (uint32_t)((wr32 + mt*16 + a_r)*80 + kk*32 + a_c);
                LDMX4(af[mt], ad);
            }
#pragma unroll
            for (int np = 0; np < 2; np++) {
                uint32_t bd = bS[buf] + (uint32_t)((wc32 + np*16 + b_r)*80 + kk*32 + b_c);
                LDMX4(bfr[np], bd);
            }
#pragma unroll
            for (int mt = 0; mt < 2; mt++)
#pragma unroll
                for (int nt = 0; nt < 4; nt++)
                    MMA16816(acc[mt][nt], af[mt], bfr[nt>>1][(nt&1)*2], bfr[nt>>1][(nt&1)*2+1]);
        }
        if (more) {
            const int nb = buf ^ 1;
#pragma unroll
            for (int i = 0; i < 2; i++) {
                int idx = t + i*256, row = idx >> 2, q = idx & 3;
                *(uint4*)(Ash[nb] + row*80 + q*16) = va[i];
            }
            { int row = t >> 2, q = t & 3;
              *(uint4*)(Bsh[nb] + row*80 + q*16) = vb; }
            __syncthreads();
        }
    }

#pragma unroll
    for (int mt = 0; mt < 2; mt++) {
#pragma unroll
        for (int h = 0; h < 2; h++) {
            const int m = m0 + wr32 + mt*16 + g + 8*h;
#pragma unroll
            for (int nt = 0; nt < 4; nt++) {
                const int n = n0 + wc32 + nt*8 + 2*tg;
                float2 r = { acc[mt][nt][h*2], acc[mt][nt][h*2+1] };
                r.x += bias[n]; r.y += bias[n+1];
                const int sect = n >> 8, cc = n & 255;
                if (sect == 0) {
                    __align__(4) hf hh[2] = { __float2half_rn(r.x), __float2half_rn(r.y) };
                    *(uint32_t*)&Qh[(size_t)m*HID_ + cc] = *(uint32_t*)hh;
                } else if (sect == 1) {
                    __align__(4) hf hh[2] = { __float2half_rn(r.x), __float2half_rn(r.y) };
                    *(uint32_t*)&Kh[(size_t)m*HID_ + cc] = *(uint32_t*)hh;
                } else {
                    Vth[(size_t)cc * N_ + m]     = __float2half_rn(r.x);
                    Vth[(size_t)(cc+1) * N_ + m] = __float2half_rn(r.y);
                }
            }
        }
    }
}

// ---- shared mma-core macro (128x128 kernels) ----
#define COMPUTE32(abase, bbase)                                                     \
    _Pragma("unroll")                                                               \
    for (int kk = 0; kk < 2; kk++) {                                                \
        uint32_t af[4][4], bfr[2][4];                                               \
        _Pragma("unroll")                                                           \
        for (int mt = 0; mt < 4; mt++) {                                            \
            uint32_t ad = (abase) + (uint32_t)((wr64 + mt*16 + a_r)*80 + kk*32 + a_c); \
            LDMX4(af[mt], ad);                                                      \
        }                                                                           \
        _Pragma("unroll")                                                           \
        for (int np = 0; np < 2; np++) {                                            \
            uint32_t bd = (bbase) + (uint32_t)((wc32 + np*16 + b_r)*80 + kk*32 + b_c); \
            LDMX4(bfr[np], bd);                                                     \
        }                                                                           \
        _Pragma("unroll")                                                           \
        for (int mt = 0; mt < 4; mt++)                                              \
            _Pragma("unroll")                                                       \
            for (int nt = 0; nt < 4; nt++)                                          \
                MMA16816(acc[mt][nt], af[mt], bfr[nt>>1][(nt&1)*2], bfr[nt>>1][(nt&1)*2+1]); \
    }

// ================= scores via fp16 mma, single pass (q single, k single) =================
__global__ __launch_bounds__(256) void scores_mma(
    const hf* __restrict__ qh, const hf* __restrict__ kh,
    const float* __restrict__ xyz,
    const uint32_t* __restrict__ Mb,
    float* __restrict__ S)
{
    __shared__ __align__(16) char Ash[2][128*80];
    __shared__ __align__(16) char Bsh[2][128*80];
    __shared__ float gix[128*3], gisq[128], giy[128];
    __shared__ float gjx[128*3], gjsq[128], gjy[128];
    const int t = threadIdx.x, lane = t & 31, wid = t >> 5;
    const int wr64 = (wid >> 2) * 64, wc32 = (wid & 3) * 32;
    const int g = lane >> 2, tg = lane & 3;
    const int a_r = ((lane >> 3) & 1) * 8 + (lane & 7);
    const int a_c = (lane >> 4) * 16;
    const int b_r = ((lane >> 4) & 1) * 8 + (lane & 7);
    const int b_c = ((lane >> 3) & 1) * 16;
    const int i0 = blockIdx.y * 128, j0 = blockIdx.x * 128;
    const int lrow = t >> 2, lq = t & 3;

    if (t < 128) {
        float a = xyz[(i0+t)*3+0], b = xyz[(i0+t)*3+1], c = xyz[(i0+t)*3+2];
        gix[t*3+0]=a; gix[t*3+1]=b; gix[t*3+2]=c;
        gisq[t] = fmaf(c,c,fmaf(b,b,a*a));
        giy[t]  = g_y[i0+t];
    } else {
        int u = t - 128;
        float a = xyz[(j0+u)*3+0], b = xyz[(j0+u)*3+1], c = xyz[(j0+u)*3+2];
        gjx[u*3+0]=a; gjx[u*3+1]=b; gjx[u*3+2]=c;
        gjsq[u] = fmaf(c,c,fmaf(b,b,a*a));
        gjy[u]  = g_y[j0+u];
    }

    uint32_t aS[2] = { smem_u32(Ash[0]), smem_u32(Ash[1]) };
    uint32_t bS[2] = { smem_u32(Bsh[0]), smem_u32(Bsh[1]) };
    float acc[4][4][4] = {};

    uint4 va[2], vb[2];
#pragma unroll
    for (int r = 0; r < 2; r++) {
        int row = lrow + r*64;
        va[r] = *(const uint4*)(qh + (size_t)(i0+row)*HID_ + lq*8);
        vb[r] = *(const uint4*)(kh + (size_t)(j0+row)*HID_ + lq*8);
    }
#pragma unroll
    for (int r = 0; r < 2; r++) {
        int row = lrow + r*64;
        *(uint4*)(Ash[0] + row*80 + lq*16) = va[r];
        *(uint4*)(Bsh[0] + row*80 + lq*16) = vb[r];
    }
    __syncthreads();

    const int NC = 8;   // single pass, K=256
    for (int c = 0; c < NC; c++) {
        const int buf = c & 1;
        if (c + 1 < NC) {
            const int kc = c + 1;
#pragma unroll
            for (int r = 0; r < 2; r++) {
                int row = lrow + r*64;
                va[r] = *(const uint4*)(qh + (size_t)(i0+row)*HID_ + kc*32 + lq*8);
                vb[r] = *(const uint4*)(kh + (size_t)(j0+row)*HID_ + kc*32 + lq*8);
            }
        }
        COMPUTE32(aS[buf], bS[buf]);
        if (c + 1 < NC) {
            const int nb = buf ^ 1;
#pragma unroll
            for (int r = 0; r < 2; r++) {
                int row = lrow + r*64;
                *(uint4*)(Ash[nb] + row*80 + lq*16) = va[r];
                *(uint4*)(Bsh[nb] + row*80 + lq*16) = vb[r];
            }
            __syncthreads();
        }
    }

#pragma unroll
    for (int mt = 0; mt < 4; mt++) {
#pragma unroll
        for (int h = 0; h < 2; h++) {
            const int li = wr64 + mt*16 + g + 8*h;
            const int gi = i0 + li;
            const float xa = gix[li*3], xbv = gix[li*3+1], xc = gix[li*3+2];
            const float sqa = gisq[li], ya = giy[li];
            const size_t rb = (size_t)gi * N_;
            const uint32_t wbits = Mb[(size_t)gi * (N_/32) + ((j0 + wc32) >> 5)];
#pragma unroll
            for (int nt = 0; nt < 4; nt++) {
                const int lj0 = wc32 + nt*8 + 2*tg;
                float2 r;
#pragma unroll
                for (int e = 0; e < 2; e++) {
                    const int lj = lj0 + e;
                    const int bitpos = nt*8 + 2*tg + e;
                    float dot = fmaf(xc, gjx[lj*3+2], fmaf(xbv, gjx[lj*3+1], xa * gjx[lj*3]));
                    float dist2 = (sqa + gjsq[lj]) - 2.0f * dot;
                    bool ok = ((wbits >> bitpos) & 1u) && (dist2 <= 100.0f);
                    float av = acc[mt][nt][h*2 + e];
                    ((float*)&r)[e] = ok ? (av * 0.0625f - fabsf(ya - gjy[lj])) : NEG_;
                }
                *(float2*)&S[rb + j0 + lj0] = r;
            }
        }
    }
}

// ================= attn@V via fp16 mma, single-pass, split-K z ======
__global__ __launch_bounds__(256) void attnv_mma(
    const hf* __restrict__ Sh,
    const hf* __restrict__ Vth,
    float* __restrict__ Cpart)
{
    __shared__ __align__(16) char Ash[2][128*80];
    __shared__ __align__(16) char Bsh[2][128*80];
    const int t = threadIdx.x, lane = t & 31, wid = t >> 5;
    const int wr64 = (wid >> 2) * 64, wc32 = (wid & 3) * 32;
    const int g = lane >> 2, tg = lane & 3;
    const int a_r = ((lane >> 3) & 1) * 8 + (lane & 7);
    const int a_c = (lane >> 4) * 16;
    const int b_r = ((lane >> 4) & 1) * 8 + (lane & 7);
    const int b_c = ((lane >> 3) & 1) * 16;
    const int m0 = blockIdx.y * 128, n0 = blockIdx.x * 128;
    const int kbase = blockIdx.z * (N_ / KZ_);
    const int lrow = t >> 2, lq = t & 3;

    uint32_t aS[2] = { smem_u32(Ash[0]), smem_u32(Ash[1]) };
    uint32_t bS[2] = { smem_u32(Bsh[0]), smem_u32(Bsh[1]) };
    float acc[4][4][4] = {};

    const int NC = (N_ / KZ_) / 32;

    uint4 va[2], vb[2];
#pragma unroll
    for (int r = 0; r < 2; r++) {
        int row = lrow + r*64;
        va[r] = *(const uint4*)(Sh + (size_t)(m0+row)*N_ + kbase + lq*8);
        vb[r] = *(const uint4*)(Vth + (size_t)(n0+row)*N_ + kbase + lq*8);
    }
#pragma unroll
    for (int r = 0; r < 2; r++) {
        int row = lrow + r*64;
        *(uint4*)(Ash[0] + row*80 + lq*16) = va[r];
        *(uint4*)(Bsh[0] + row*80 + lq*16) = vb[r];
    }
    __syncthreads();

    for (int c = 0; c < NC; c++) {
        const int buf = c & 1;
        if (c + 1 < NC) {
            const int kc = c + 1;
#pragma unroll
            for (int r = 0; r < 2; r++) {
                int row = lrow + r*64;
                va[r] = *(const uint4*)(Sh + (size_t)(m0+row)*N_ + kbase + kc*32 + lq*8);
                vb[r] = *(const uint4*)(Vth + (size_t)(n0+row)*N_ + kbase + kc*32 + lq*8);
            }
        }
        COMPUTE32(aS[buf], bS[buf]);
        if (c + 1 < NC) {
            const int nb = buf ^ 1;
#pragma unroll
            for (int r = 0; r < 2; r++) {
                int row = lrow + r*64;
                *(uint4*)(Ash[nb] + row*80 + lq*16) = va[r];
                *(uint4*)(Bsh[nb] + row*80 + lq*16) = vb[r];
            }
            __syncthreads();
        }
    }

    float* Cz = Cpart + (size_t)blockIdx.z * N_ * HID_;
#pragma unroll
    for (int mt = 0; mt < 4; mt++) {
#pragma unroll
        for (int h = 0; h < 2; h++) {
            const int m = m0 + wr64 + mt*16 + g + 8*h;
            const size_t rb = (size_t)m * HID_;
#pragma unroll
            for (int nt = 0; nt < 4; nt++) {
                const int n = n0 + wc32 + nt*8 + 2*tg;
                float2 r = { acc[mt][nt][h*2], acc[mt][nt][h*2 + 1] };
                *(float2*)&Cz[rb + n] = r;
            }
        }
    }
}

__global__ void combine_parts(const float* __restrict__ P,
                              hf* __restrict__ Hh, hf* __restrict__ Hl)
{
    int i = blockIdx.x * blockDim.x + threadIdx.x;
    const size_t n = (size_t)N_ * HID_;
    float4 a = *(const float4*)&P[(size_t)i*4];
    float4 b = *(const float4*)&P[n + (size_t)i*4];
    float4 c = *(const float4*)&P[2*n + (size_t)i*4];
    float4 d = *(const float4*)&P[3*n + (size_t)i*4];
    float rv[4] = { a.x+b.x+c.x+d.x, a.y+b.y+c.y+d.y, a.z+b.z+c.z+d.z, a.w+b.w+c.w+d.w };
    __align__(8) hf hh[4], ll[4];
#pragma unroll
    for (int e = 0; e < 4; e++) split1h(rv[e], hh[e], ll[e]);
    *(uint2*)&Hh[(size_t)i*4] = *(uint2*)hh;
    *(uint2*)&Hl[(size_t)i*4] = *(uint2*)ll;
}

// ---------------- softmax + attn@xyz + fp16 store (shuffle reductions) ----------------
__global__ void softmax_xyz(const float* __restrict__ S,
                            hf* __restrict__ Sh,
                            const float* __restrict__ xs, const float* __restrict__ ys,
                            const float* __restrict__ zs, float* __restrict__ out)
{
    __shared__ float red[8];
    __shared__ float r3[24];
    const int row = blockIdx.x, t = threadIdx.x, lane = t & 31, wid = t >> 5;
    const float* p = S + (size_t)row * N_;
    float4 v[4];
    float mx = -1e30f;
#pragma unroll
    for (int c = 0; c < 4; c++) {
        v[c] = *(const float4*)&p[c*1024 + t*4];
        mx = fmaxf(mx, fmaxf(fmaxf(v[c].x, v[c].y), fmaxf(v[c].z, v[c].w)));
    }
#pragma unroll
    for (int o = 16; o > 0; o >>= 1) mx = fmaxf(mx, __shfl_xor_sync(0xffffffffu, mx, o));
    if (lane == 0) red[wid] = mx;
    __syncthreads();
    mx = red[0];
#pragma unroll
    for (int w = 1; w < 8; w++) mx = fmaxf(mx, red[w]);
    __syncthreads();

    float sum = 0.0f;
#pragma unroll
    for (int c = 0; c < 4; c++) {
        v[c].x = fast_exp(v[c].x - mx); v[c].y = fast_exp(v[c].y - mx);
        v[c].z = fast_exp(v[c].z - mx); v[c].w = fast_exp(v[c].w - mx);
        sum += v[c].x + v[c].y + v[c].z + v[c].w;
    }
#pragma unroll
    for (int o = 16; o > 0; o >>= 1) sum += __shfl_xor_sync(0xffffffffu, sum, o);
    if (lane == 0) red[wid] = sum;
    __syncthreads();
    sum = red[0];
#pragma unroll
    for (int w = 1; w < 8; w++) sum += red[w];
    const float inv = 1.0f / sum;

    float a0 = 0.f, a1 = 0.f, a2 = 0.f;
#pragma unroll
    for (int c = 0; c < 4; c++) {
        v[c].x *= inv; v[c].y *= inv; v[c].z *= inv; v[c].w *= inv;
        float vv[4] = { v[c].x, v[c].y, v[c].z, v[c].w };
        __align__(8) hf vh[4];
#pragma unroll
        for (int e = 0; e < 4; e++) vh[e] = __float2half_rn(vv[e]);
        const size_t off = (size_t)row * N_ + c*1024 + t*4;
        *(uint2*)&Sh[off] = *(uint2*)vh;
        const int j = c*1024 + t*4;
        a0 = fmaf(v[c].x, xs[j], fmaf(v[c].y, xs[j+1], fmaf(v[c].z, xs[j+2], fmaf(v[c].w, xs[j+3], a0))));
        a1 = fmaf(v[c].x, ys[j], fmaf(v[c].y, ys[j+1], fmaf(v[c].z, ys[j+2], fmaf(v[c].w, ys[j+3], a1))));
        a2 = fmaf(v[c].x, zs[j], fmaf(v[c].y, zs[j+1], fmaf(v[c].z, zs[j+2], fmaf(v[c].w, zs[j+3], a2))));
    }
#pragma unroll
    for (int o = 16; o > 0; o >>= 1) {
        a0 += __shfl_xor_sync(0xffffffffu, a0, o);
        a1 += __shfl_xor_sync(0xffffffffu, a1, o);
        a2 += __shfl_xor_sync(0xffffffffu, a2, o);
    }
    if (lane == 0) { r3[wid*3+0] = a0; r3[wid*3+1] = a1; r3[wid*3+2] = a2; }
    __syncthreads();
    if (t == 0) {
        float s0 = 0.f, s1 = 0.f, s2 = 0.f;
#pragma unroll
        for (int w = 0; w < 8; w++) { s0 += r3[w*3]; s1 += r3[w*3+1]; s2 += r3[w*3+2]; }
        out[row*3+0] = s0; out[row*3+1] = s1; out[row*3+2] = s2;
    }
}

__global__ void xyz2soa(const float* __restrict__ xyz, float* __restrict__ xs,
                        float* __restrict__ ys, float* __restrict__ zs)
{
    int i = blockIdx.x * blockDim.x + threadIdx.x;
    if (i < N_) { xs[i] = xyz[3*i]; ys[i] = xyz[3*i+1]; zs[i] = xyz[3*i+2]; }
}

// ---------------- GAT pieces ----------------
__global__ void compute_elr(const float* __restrict__ hl, const float* __restrict__ al,
                            const float* __restrict__ ar)
{
    int idx = blockIdx.x * blockDim.x + threadIdx.x;
    if (idx >= N_*4) return;
    int node = idx >> 2, h = idx & 3;
    const float* row = hl + (size_t)node * HID_ + h * 64;
    float sl = 0.f, sr = 0.f;
#pragma unroll 8
    for (int d = 0; d < 64; d++) {
        float v = row[d];
        sl = fmaf(v, al[h*64+d], sl);
        sr = fmaf(v, ar[h*64+d], sr);
    }
    g_el[idx] = sl; g_er[idx] = sr;
}

__global__ void zero_cnt() { int i = blockIdx.x*blockDim.x + threadIdx.x; if (i < N_) g_cnt[i] = 0; }
__global__ void count_edges(const int* __restrict__ dst) {
    int e = blockIdx.x*blockDim.x + threadIdx.x; if (e < E_) atomicAdd(&g_cnt[dst[e]], 1);
}
__global__ void scan4096() {
    __shared__ int part[1024];
    int t = threadIdx.x, base = t * 4;
    int a0 = g_cnt[base], a1 = g_cnt[base+1], a2 = g_cnt[base+2], a3 = g_cnt[base+3];
    int s = a0 + a1 + a2 + a3;
    part[t] = s; __syncthreads();
    for (int off = 1; off < 1024; off <<= 1) {
        int v = (t >= off) ? part[t-off] : 0;
        __syncthreads();
        part[t] += v;
        __syncthreads();
    }
    int excl = part[t] - s;
    g_rowptr[base+0] = excl;           g_cur[base+0] = excl;
    g_rowptr[base+1] = excl+a0;        g_cur[base+1] = excl+a0;
    g_rowptr[base+2] = excl+a0+a1;     g_cur[base+2] = excl+a0+a1;
    g_rowptr[base+3] = excl+a0+a1+a2;  g_cur[base+3] = excl+a0+a1+a2;
    if (t == 1023) g_rowptr[4096] = part[1023];
}
__global__ void scatter_edges(const int* __restrict__ src, const int* __restrict__ dst) {
    int e = blockIdx.x*blockDim.x + threadIdx.x;
    if (e < E_) { int p = atomicAdd(&g_cur[dst[e]], 1); g_psrc[p] = src[e]; }
}

__global__ void gat_aggregate(const float* __restrict__ hl, float* __restrict__ xg)
{
    const int node = (blockIdx.x * blockDim.x + threadIdx.x) >> 5;
    const int lane = threadIdx.x & 31;
    if (node >= N_) return;
    const int beg = g_rowptr[node], end = g_rowptr[node+1];
    const float er_i = (lane < 4) ? g_er[node*4 + lane] : 0.f;
    float m = -1e30f;
    for (int p = beg; p < end; p++) {
        int s = g_psrc[p];
        if (lane < 4) {
            float v = g_el[s*4 + lane] + er_i;
            float e = (v > 0.f) ? v : 0.2f * v;
            m = fmaxf(m, e);
        }
    }
    float m0 = __shfl_sync(0xffffffffu, m, 0), m1 = __shfl_sync(0xffffffffu, m, 1);
    float m2 = __shfl_sync(0xffffffffu, m, 2), m3 = __shfl_sync(0xffffffffu, m, 3);
    const int myh = lane >> 3;
    float4 acc0 = {0,0,0,0}, acc1 = {0,0,0,0};
    float z = 0.f;
    for (int p = beg; p < end; p++) {
        int s = g_psrc[p];
        float w = 0.f;
        if (lane < 4) {
            float v = g_el[s*4 + lane] + er_i;
            float e = (v > 0.f) ? v : 0.2f * v;
            float mm = (lane==0)?m0:(lane==1)?m1:(lane==2)?m2:m3;
            w = fast_exp(e - mm);
            z += w;
        }
        float w0 = __shfl_sync(0xffffffffu, w, 0), w1 = __shfl_sync(0xffffffffu, w, 1);
        float w2 = __shfl_sync(0xffffffffu, w, 2), w3 = __shfl_sync(0xffffffffu, w, 3);
        float wm = (myh==0)?w0:(myh==1)?w1:(myh==2)?w2:w3;
        const float4* hp = (const float4*)(hl + (size_t)s * HID_ + lane * 8);
        float4 hv0 = hp[0], hv1 = hp[1];
        acc0.x=fmaf(wm,hv0.x,acc0.x); acc0.y=fmaf(wm,hv0.y,acc0.y);
        acc0.z=fmaf(wm,hv0.z,acc0.z); acc0.w=fmaf(wm,hv0.w,acc0.w);
        acc1.x=fmaf(wm,hv1.x,acc1.x); acc1.y=fmaf(wm,hv1.y,acc1.y);
        acc1.z=fmaf(wm,hv1.z,acc1.z); acc1.w=fmaf(wm,hv1.w,acc1.w);
    }
    float z0 = __shfl_sync(0xffffffffu, z, 0), z1 = __shfl_sync(0xffffffffu, z, 1);
    float z2 = __shfl_sync(0xffffffffu, z, 2), z3 = __shfl_sync(0xffffffffu, z, 3);
    float zm = (myh==0)?z0:(myh==1)?z1:(myh==2)?z2:z3;
    float inv = 1.0f / (zm + 1e-9f);
    acc0.x*=inv; acc0.y*=inv; acc0.z*=inv; acc0.w*=inv;
    acc1.x*=inv; acc1.y*=inv; acc1.z*=inv; acc1.w*=inv;
    float4* op = (float4*)(xg + (size_t)node * HID_ + lane * 8);
    op[0] = acc0; op[1] = acc1;
}

__global__ void pack_support(const float* __restrict__ xg, const float* __restrict__ h0,
                             hf* __restrict__ suph, hf* __restrict__ supl)
{
    int i = blockIdx.x * blockDim.x + threadIdx.x;
    if (i >= N_ * 512) return;
    int r = i >> 9, c = i & 511;
    float v = (c < 256) ? xg[(size_t)r*256 + c] : h0[(size_t)r*256 + (c-256)];
    hf h, l; split1h(v, h, l);
    suph[i] = h; supl[i] = l;
}

__global__ void yhat_k(const float* __restrict__ x, const float* __restrict__ W,
                       const float* __restrict__ b)
{
    int i = blockIdx.x * blockDim.x + threadIdx.x;
    if (i >= N_) return;
    const float* r = x + (size_t)i * HID_;
    float l0 = b[0], l1 = b[1];
#pragma unroll 8
    for (int d = 0; d < HID_; d++) {
        float v = r[d];
        l0 = fmaf(v, W[2*d+0], l0);
        l1 = fmaf(v, W[2*d+1], l1);
    }
    g_y[i] = 1.0f / (1.0f + expf(l0 - l1));
}

__global__ void cls_k(const float* __restrict__ x, const float* __restrict__ W,
                      const float* __restrict__ b, float* __restrict__ out)
{
    int i = blockIdx.x * blockDim.x + threadIdx.x;
    if (i >= N_) return;
    const float* r = x + (size_t)i * HID_;
    float l0 = b[0], l1 = b[1];
#pragma unroll 8
    for (int d = 0; d < HID_; d++) {
        float v = r[d];
        l0 = fmaf(v, W[2*d+0], l0);
        l1 = fmaf(v, W[2*d+1], l1);
    }
    out[2*i+0] = l0;
    out[2*i+1] = l1;
}

// ---------------- host orchestration ----------------
extern "C" void kernel_launch(void* const* d_in, const int* in_sizes, int n_in,
                              void* d_out, int out_size)
{
    const float* feat   = (const float*)d_in[0];
    const float* xyz_in = (const float*)d_in[1];
    const int*   src    = (const int*)  d_in[2];
    const int*   dst    = (const int*)  d_in[3];
    const void*  dmask  = d_in[4];
    const void*  bmask  = d_in[5];
    const float* fcW  = (const float*)d_in[6];
    const float* fcb  = (const float*)d_in[7];
    const float* gatW = (const float*)d_in[8];
    const float* al   = (const float*)d_in[9];
    const float* ar   = (const float*)d_in[10];
    const float* gcW  = (const float*)d_in[11];
    const float* cgW  = (const float*)d_in[12];
    const float* cgb  = (const float*)d_in[13];
    const float* qW   = (const float*)d_in[14];
    const float* qb_  = (const float*)d_in[15];
    const float* kW   = (const float*)d_in[16];
    const float* kb_  = (const float*)d_in[17];
    const float* vW   = (const float*)d_in[18];
    const float* vb_  = (const float*)d_in[19];
    const float* oW   = (const float*)d_in[20];
    const float* ob   = (const float*)d_in[21];
    const float* clsW = (const float*)d_in[22];
    const float* clsb = (const float*)d_in[23];

    float *px, *ph0, *phl, *pxg, *pS, *pxyz0, *pxyz1, *pxs, *pys, *pzs, *ppart, *pqkvb;
    uint32_t *pmb;
    hf *pxh, *pxl, *pfeath, *pfeatl, *psuph, *psupl, *phmsh, *phmsl;
    hf *pqh, *pkh, *pvth, *psh;
    hf *pfcWth, *pgatWth, *pgcWth, *pqkvWth, *poWth;
    cudaGetSymbolAddress((void**)&px,    g_x);
    cudaGetSymbolAddress((void**)&ph0,   g_h0);
    cudaGetSymbolAddress((void**)&phl,   g_hl_);
    cudaGetSymbolAddress((void**)&pxg,   g_xg);
    cudaGetSymbolAddress((void**)&pS,    g_S);
    cudaGetSymbolAddress((void**)&pmb,   g_mb);
    cudaGetSymbolAddress((void**)&pxyz0, g_xyz0);
    cudaGetSymbolAddress((void**)&pxyz1, g_xyz1);
    cudaGetSymbolAddress((void**)&pxs,   g_xs_);
    cudaGetSymbolAddress((void**)&pys,   g_ys_);
    cudaGetSymbolAddress((void**)&pzs,   g_zs_);
    cudaGetSymbolAddress((void**)&ppart, g_part);
    cudaGetSymbolAddress((void**)&pqkvb, g_qkvb);
    cudaGetSymbolAddress((void**)&pxh,   g_xh);
    cudaGetSymbolAddress((void**)&pxl,   g_xl);
    cudaGetSymbolAddress((void**)&pfeath,g_feath);
    cudaGetSymbolAddress((void**)&pfeatl,g_featl);
    cudaGetSymbolAddress((void**)&psuph, g_suph);
    cudaGetSymbolAddress((void**)&psupl, g_supl);
    cudaGetSymbolAddress((void**)&phmsh, g_hmsh);
    cudaGetSymbolAddress((void**)&phmsl, g_hmsl);
    cudaGetSymbolAddress((void**)&pqh,   g_qh);
    cudaGetSymbolAddress((void**)&pkh,   g_kh);
    cudaGetSymbolAddress((void**)&pvth,  g_vth);
    cudaGetSymbolAddress((void**)&psh,   g_sh);
    cudaGetSymbolAddress((void**)&pfcWth,  g_fcWth);
    cudaGetSymbolAddress((void**)&pgatWth, g_gatWth);
    cudaGetSymbolAddress((void**)&pgcWth,  g_gcWth);
    cudaGetSymbolAddress((void**)&pqkvWth, g_qkvWth);
    cudaGetSymbolAddress((void**)&poWth,   g_oWth);

    detect_mask_mode<<<1, 1>>>((const unsigned int*)dmask);
    maskpack<<<(N_*(N_/32))/256, 256>>>(dmask, bmask, pmb);

    wsplit_t<<<dim3(HID_/32, FEAT_/32, 1), 256>>>(fcW, pfcWth, FEAT_, HID_);
    wsplit_t<<<dim3(HID_/32, HID_/32, 4), 256>>>(gatW, pgatWth, HID_, HID_);
    wsplit_t<<<dim3(HID_/32, 2*HID_/32, 4), 256>>>(gcW, pgcWth, 2*HID_, HID_);
    wsplit_t<<<dim3(HID_/32, HID_/32, 4), 256>>>(oW, poWth, HID_, HID_);
    wsplit_ro_t<<<dim3(8, 8, 4), 256>>>(qW, pqkvWth, 0);
    wsplit_ro_t<<<dim3(8, 8, 4), 256>>>(kW, pqkvWth, 256);
    wsplit_ro_t<<<dim3(8, 8, 4), 256>>>(vW, pqkvWth, 512);
    qkvbias<<<12, 256>>>(qb_, kb_, vb_, pqkvb);
    split_hf<<<(N_*FEAT_/4)/256, 256>>>(feat, pfeath, pfeatl);

    gemm_tc64<<<dim3(HID_/64, N_/64), 256>>>(pfeath, pfeatl, pfcWth, FEAT_, HID_,
                                             fcb, 1, 1.0f, nullptr,0.f, nullptr,0.f, nullptr,0.f,
                                             px, ph0, pxh, pxl);

    zero_cnt<<<N_/256, 256>>>();
    count_edges<<<E_/256, 256>>>(dst);
    scan4096<<<1, 1024>>>();
    scatter_edges<<<E_/256, 256>>>(src, dst);

    const float ALPHA = 0.1f, LAMDA = 0.5f;
    for (int l = 0; l < 4; l++) {
        gemm_tc64<<<dim3(HID_/64, N_/64), 256>>>(pxh, pxl, pgatWth + (size_t)l*HID_*HID_,
                                                 HID_, HID_,
                                                 nullptr, 0, 1.0f, nullptr,0.f, nullptr,0.f, nullptr,0.f,
                                                 phl, nullptr, nullptr, nullptr);
        compute_elr<<<(N_*4)/256, 256>>>(phl, al + l*4*64, ar + l*4*64);
        gat_aggregate<<<N_/8, 256>>>(phl, pxg);
        pack_support<<<(N_*512)/256, 256>>>(pxg, ph0, psuph, psupl);
        float theta = fminf(1.0f, logf(LAMDA / (float)(l + 1) + 1.0f));
        gemm_tc64<<<dim3(HID_/64, N_/64), 256>>>(psuph, psupl, pgcWth + (size_t)l*2*HID_*HID_,
                                                 2*HID_, HID_,
                                                 nullptr, 0, theta,
                                                 pxg, (1.0f-theta)*(1.0f-ALPHA),
                                                 ph0, (1.0f-theta)*ALPHA,
                                                 px,  1.0f,
                                                 px, nullptr, pxh, pxl);
    }

    yhat_k<<<N_/256, 256>>>(px, cgW, cgb);

    const float* xyz_cur = xyz_in;
    float* xyz_buf[2] = { pxyz0, pxyz1 };
    for (int l = 0; l < 4; l++) {
        qkv_tc<<<dim3(768/64, N_/128), 256>>>(pxh, pxl,
                                              pqkvWth + (size_t)l*768*HID_,
                                              pqkvb + l*768,
                                              pqh, pkh, pvth);
        scores_mma<<<dim3(N_/128, N_/128), 256>>>(pqh, pkh, xyz_cur, pmb, pS);
        xyz2soa<<<N_/256, 256>>>(xyz_cur, pxs, pys, pzs);
        softmax_xyz<<<N_, 256>>>(pS, psh, pxs, pys, pzs, xyz_buf[l & 1]);
        attnv_mma<<<dim3(HID_/128, N_/128, KZ_), 256>>>(psh, pvth, ppart);
        combine_parts<<<(N_*HID_/4)/256, 256>>>(ppart, phmsh, phmsl);
        gemm_tc64<<<dim3(HID_/64, N_/64), 256>>>(phmsh, phmsl, poWth + (size_t)l*HID_*HID_,
                                                 HID_, HID_,
                                                 ob + l*HID_, 0, 1.0f,
                                                 px, 1.0f, nullptr,0.f, nullptr,0.f,
                                                 px, nullptr, pxh, pxl);
        xyz_cur = xyz_buf[l & 1];
    }

    cls_k<<<N_/256, 256>>>(px, clsW, clsb, (float*)d_out);
}

// round 17
// speedup vs baseline: 1.2196x; 1.0891x over previous
#include <cuda_runtime.h>
#include <cuda_fp16.h>
#include <math.h>
#include <stdint.h>

#define N_    4096
#define E_    131072
#define FEAT_ 64
#define HID_  256
#define NEG_  (-1e9f)
#define KZ_   4

typedef __half hf;

// ---------------- scratch ----------------
__device__ float g_h0 [N_*HID_];
__device__ float g_x  [N_*HID_];
__device__ float g_hl_[N_*HID_];
__device__ float g_xg [N_*HID_];
__device__ float g_part[(size_t)KZ_*N_*HID_];
__device__ float g_S  [(size_t)N_*N_];
__device__ uint32_t g_mb[(size_t)N_*N_/32];
__device__ hf g_xh[N_*HID_], g_xl[N_*HID_];
__device__ hf g_feath[N_*FEAT_], g_featl[N_*FEAT_];
__device__ hf g_suph[N_*2*HID_], g_supl[N_*2*HID_];
__device__ hf g_hmsh[N_*HID_], g_hmsl[N_*HID_];
__device__ hf g_qh[N_*HID_];
__device__ hf g_kh[N_*HID_];
__device__ hf g_vth[HID_*N_];
__device__ hf g_sh[(size_t)N_*N_];
__device__ hf g_fcWth[HID_*FEAT_];
__device__ hf g_gatWth[4*HID_*HID_];
__device__ hf g_gcWth[4*HID_*2*HID_];
__device__ hf g_qkvWth[4*768*HID_];
__device__ float g_qkvb[4*768];
__device__ hf g_oWth[4*HID_*HID_];
__device__ float g_el [N_*4];
__device__ float g_er [N_*4];
__device__ float g_y  [N_];
__device__ float g_xyz0[N_*3];
__device__ float g_xyz1[N_*3];
__device__ float g_xs_[N_], g_ys_[N_], g_zs_[N_];
__device__ int   g_cnt[N_];
__device__ int   g_rowptr[N_+1];
__device__ int   g_cur[N_];
__device__ int   g_psrc[E_];
__device__ int   g_maskmode;

// ---------------- helpers ----------------
__device__ __forceinline__ uint32_t smem_u32(const void* p) {
    uint32_t a;
    asm("{ .reg .u64 t; cvta.to.shared.u64 t, %1; cvt.u32.u64 %0, t; }" : "=r"(a) : "l"(p));
    return a;
}
#define LDMX4(r, a) \
    asm volatile("ldmatrix.sync.aligned.m8n8.x4.shared.b16 {%0,%1,%2,%3}, [%4];" \
        : "=r"((r)[0]), "=r"((r)[1]), "=r"((r)[2]), "=r"((r)[3]) : "r"(a))
#define MMA16816(c, a, b0, b1) \
    asm volatile("mma.sync.aligned.m16n8k16.row.col.f32.f16.f16.f32 " \
        "{%0,%1,%2,%3}, {%4,%5,%6,%7}, {%8,%9}, {%0,%1,%2,%3};" \
        : "+f"((c)[0]), "+f"((c)[1]), "+f"((c)[2]), "+f"((c)[3]) \
        : "r"((a)[0]), "r"((a)[1]), "r"((a)[2]), "r"((a)[3]), "r"(b0), "r"(b1))
#define CP16(sa, gp) \
    asm volatile("cp.async.cg.shared.global [%0], [%1], 16;" :: "r"(sa), "l"(gp))
#define CPCOMMIT() asm volatile("cp.async.commit_group;" ::: "memory")
#define CPWAIT0()  asm volatile("cp.async.wait_group 0;" ::: "memory")

__device__ __forceinline__ void split1h(float v, hf& h, hf& l) {
    h = __float2half_rn(v);
    l = __float2half_rn(v - __half2float(h));
}

__device__ __forceinline__ float fast_exp(float x) {
    float t = x * 1.4426950408889634f;
    t = fmaxf(t, -126.0f);
    float z = t + 12582912.0f;
    float n = z - 12582912.0f;
    float f = t - n;
    float p = 1.5404e-4f;
    p = fmaf(p, f, 1.33336e-3f);
    p = fmaf(p, f, 9.61813e-3f);
    p = fmaf(p, f, 5.550411e-2f);
    p = fmaf(p, f, 2.4022651e-1f);
    p = fmaf(p, f, 6.9314718e-1f);
    p = fmaf(p, f, 1.0f);
    int ni = __float_as_int(z) - 0x4B400000;
    float sc = __int_as_float((ni + 127) << 23);
    return p * sc;
}

__global__ void detect_mask_mode(const unsigned int* __restrict__ m) {
    bool allbin = true, anyfloat = false;
    for (int i = 0; i < 1024; i++) {
        unsigned int w = m[i];
        if (w == 0x3f800000u) anyfloat = true;
        if (w > 1u) allbin = false;
    }
    g_maskmode = anyfloat ? 2 : (allbin ? 1 : 0);
}
__device__ __forceinline__ bool mask_at(const void* p, size_t i, int mode) {
    if (mode == 0) return ((const unsigned char*)p)[i] != 0;
    if (mode == 1) return ((const int*)p)[i] != 0;
    return ((const float*)p)[i] != 0.0f;
}

__global__ void maskpack(const void* __restrict__ dmask, const void* __restrict__ bmask,
                         uint32_t* __restrict__ out)
{
    int w = blockIdx.x * 256 + threadIdx.x;
    const int mode = g_maskmode;
    uint32_t bits = 0;
    if (mode == 0) {
        const uint4* d4 = (const uint4*)((const char*)dmask + (size_t)w * 32);
        const uint4* b4 = (const uint4*)((const char*)bmask + (size_t)w * 32);
        uint4 d0 = d4[0], d1 = d4[1], b0 = b4[0], b1 = b4[1];
        uint32_t dw[8] = {d0.x, d0.y, d0.z, d0.w, d1.x, d1.y, d1.z, d1.w};
        uint32_t bw[8] = {b0.x, b0.y, b0.z, b0.w, b1.x, b1.y, b1.z, b1.w};
#pragma unroll
        for (int q = 0; q < 8; q++)
#pragma unroll
            for (int e = 0; e < 4; e++)
                if (((dw[q] >> (8*e)) & 0xFFu) && ((bw[q] >> (8*e)) & 0xFFu))
                    bits |= 1u << (q*4 + e);
    } else {
        const size_t base = (size_t)w * 32;
#pragma unroll 4
        for (int e = 0; e < 32; e++)
            if (mask_at(dmask, base + e, mode) && mask_at(bmask, base + e, mode))
                bits |= (1u << e);
    }
    out[w] = bits;
}

__global__ void split_hf(const float* __restrict__ X, hf* __restrict__ Xh, hf* __restrict__ Xl)
{
    int i = blockIdx.x * blockDim.x + threadIdx.x;
    float4 x = *(const float4*)&X[(size_t)i*4];
    float xv[4] = {x.x, x.y, x.z, x.w};
    __align__(8) hf h[4], l[4];
#pragma unroll
    for (int e = 0; e < 4; e++) split1h(xv[e], h[e], l[e]);
    *(uint2*)&Xh[(size_t)i*4] = *(uint2*)h;
    *(uint2*)&Xl[(size_t)i*4] = *(uint2*)l;
}

// tiled transpose-convert: W [nmat][K,N] fp32 -> Wt [nmat][N,K] fp16
__global__ void wsplit_t(const float* __restrict__ W, hf* __restrict__ Wth, int K, int N)
{
    __shared__ hf tile[32][33];
    const int mat = blockIdx.z;
    const int k0 = blockIdx.y * 32, n0 = blockIdx.x * 32;
    const int tx = threadIdx.x & 31, ty = threadIdx.x >> 5;
#pragma unroll
    for (int r = ty; r < 32; r += 8)
        tile[r][tx] = __float2half_rn(W[((size_t)mat * K + k0 + r) * N + n0 + tx]);
    __syncthreads();
#pragma unroll
    for (int r = ty; r < 32; r += 8)
        Wth[((size_t)mat * N + n0 + r) * K + k0 + tx] = tile[tx][r];
}

__global__ void wsplit_ro_t(const float* __restrict__ W, hf* __restrict__ Wth, int ro)
{
    __shared__ hf tile[32][33];
    const int l = blockIdx.z;
    const int k0 = blockIdx.y * 32, n0 = blockIdx.x * 32;
    const int tx = threadIdx.x & 31, ty = threadIdx.x >> 5;
#pragma unroll
    for (int r = ty; r < 32; r += 8)
        tile[r][tx] = __float2half_rn(W[((size_t)l * 256 + k0 + r) * 256 + n0 + tx]);
    __syncthreads();
#pragma unroll
    for (int r = ty; r < 32; r += 8)
        Wth[((size_t)l * 768 + ro + n0 + r) * 256 + k0 + tx] = tile[tx][r];
}

__global__ void qkvbias(const float* __restrict__ qb, const float* __restrict__ kb,
                        const float* __restrict__ vb, float* __restrict__ out)
{
    int idx = blockIdx.x * 256 + threadIdx.x;
    if (idx >= 4*768) return;
    int l = idx / 768, c = idx % 768;
    int sect = c >> 8, cc = c & 255;
    out[idx] = (sect == 0) ? qb[l*256+cc] : (sect == 1) ? kb[l*256+cc] : vb[l*256+cc];
}

// ================= gemm_tc64: 64x64 tile fp16-mma, 2-pass, cp.async pipeline ===========
__global__ __launch_bounds__(256) void gemm_tc64(
    const hf* __restrict__ Ah, const hf* __restrict__ Al,
    const hf* __restrict__ Bh,
    int K, int Nc,
    const float* __restrict__ bias, int relu, float cacc,
    const float* __restrict__ X1, float c1,
    const float* __restrict__ X2, float c2,
    const float* __restrict__ X3, float c3,
    float* __restrict__ C, float* __restrict__ C2,
    hf* __restrict__ Ch, hf* __restrict__ Cl)
{
    __shared__ __align__(16) char Ash[2][64*80];
    __shared__ __align__(16) char Bsh[2][64*80];
    const int t = threadIdx.x, lane = t & 31, wid = t >> 5;
    const int wr32 = (wid >> 2) * 32, wc16 = (wid & 3) * 16;
    const int g = lane >> 2, tg = lane & 3;
    const int a_r = ((lane >> 3) & 1) * 8 + (lane & 7);
    const int a_c = (lane >> 4) * 16;
    const int b_r = ((lane >> 4) & 1) * 8 + (lane & 7);
    const int b_c = ((lane >> 3) & 1) * 16;
    const int m0 = blockIdx.y * 64, n0 = blockIdx.x * 64;
    const int lrow = t >> 2, lq = t & 3;

    uint32_t aS[2] = { smem_u32(Ash[0]), smem_u32(Ash[1]) };
    uint32_t bS[2] = { smem_u32(Bsh[0]), smem_u32(Bsh[1]) };
    float acc[2][2][4] = {};

    const hf* APs[2] = { Ah, Al };
    const int chunks = K >> 5;
    const int NC = 2 * chunks;

    // issue chunk 0
    CP16(aS[0] + lrow*80 + lq*16, APs[0] + (size_t)(m0+lrow)*K + lq*8);
    CP16(bS[0] + lrow*80 + lq*16, Bh + (size_t)(n0+lrow)*K + lq*8);
    CPCOMMIT();

    for (int c = 0; c < NC; c++) {
        const int buf = c & 1;
        CPWAIT0();
        __syncthreads();
        if (c + 1 < NC) {
            const int cn = c + 1;
            const int pn = cn / chunks, kn = cn % chunks;
            const int nb = buf ^ 1;
            CP16(aS[nb] + lrow*80 + lq*16, APs[pn] + (size_t)(m0+lrow)*K + kn*32 + lq*8);
            CP16(bS[nb] + lrow*80 + lq*16, Bh + (size_t)(n0+lrow)*K + kn*32 + lq*8);
            CPCOMMIT();
        }
#pragma unroll
        for (int kk = 0; kk < 2; kk++) {
            uint32_t af[2][4], bfr[4];
#pragma unroll
            for (int mt = 0; mt < 2; mt++) {
                uint32_t ad = aS[buf] + (uint32_t)((wr32 + mt*16 + a_r)*80 + kk*32 + a_c);
                LDMX4(af[mt], ad);
            }
            {
                uint32_t bd = bS[buf] + (uint32_t)((wc16 + b_r)*80 + kk*32 + b_c);
                LDMX4(bfr, bd);
            }
#pragma unroll
            for (int mt = 0; mt < 2; mt++)
#pragma unroll
                for (int nt = 0; nt < 2; nt++)
                    MMA16816(acc[mt][nt], af[mt], bfr[nt*2], bfr[nt*2+1]);
        }
    }

#pragma unroll
    for (int mt = 0; mt < 2; mt++) {
#pragma unroll
        for (int h = 0; h < 2; h++) {
            const int m = m0 + wr32 + mt*16 + g + 8*h;
            const size_t rb = (size_t)m * Nc;
#pragma unroll
            for (int nt = 0; nt < 2; nt++) {
                const int n = n0 + wc16 + nt*8 + 2*tg;
                float2 r = { acc[mt][nt][h*2], acc[mt][nt][h*2+1] };
                r.x *= cacc; r.y *= cacc;
                if (bias) { r.x += bias[n]; r.y += bias[n+1]; }
                if (X1) { float2 q = *(const float2*)&X1[rb+n];
                          r.x = fmaf(c1,q.x,r.x); r.y = fmaf(c1,q.y,r.y); }
                if (X2) { float2 q = *(const float2*)&X2[rb+n];
                          r.x = fmaf(c2,q.x,r.x); r.y = fmaf(c2,q.y,r.y); }
                if (X3) { float2 q = *(const float2*)&X3[rb+n];
                          r.x = fmaf(c3,q.x,r.x); r.y = fmaf(c3,q.y,r.y); }
                if (relu) { r.x = fmaxf(r.x, 0.f); r.y = fmaxf(r.y, 0.f); }
                if (C)  *(float2*)&C[rb+n]  = r;
                if (C2) *(float2*)&C2[rb+n] = r;
                if (Ch) {
                    __align__(4) hf h2[2], l2[2];
                    split1h(r.x, h2[0], l2[0]); split1h(r.y, h2[1], l2[1]);
                    *(uint32_t*)&Ch[rb+n] = *(uint32_t*)h2;
                    *(uint32_t*)&Cl[rb+n] = *(uint32_t*)l2;
                }
            }
        }
    }
}

// ================= qkv_tc: fused QKV GEMM, tile 128x64, cp.async pipeline ==============
__global__ __launch_bounds__(256) void qkv_tc(
    const hf* __restrict__ Ah, const hf* __restrict__ Al,
    const hf* __restrict__ Bh,
    const float* __restrict__ bias,
    hf* __restrict__ Qh, hf* __restrict__ Kh, hf* __restrict__ Vth)
{
    __shared__ __align__(16) char Ash[2][128*80];
    __shared__ __align__(16) char Bsh[2][64*80];
    const int t = threadIdx.x, lane = t & 31, wid = t >> 5;
    const int wr32 = (wid >> 1) * 32, wc32 = (wid & 1) * 32;
    const int g = lane >> 2, tg = lane & 3;
    const int a_r = ((lane >> 3) & 1) * 8 + (lane & 7);
    const int a_c = (lane >> 4) * 16;
    const int b_r = ((lane >> 4) & 1) * 8 + (lane & 7);
    const int b_c = ((lane >> 3) & 1) * 16;
    const int m0 = blockIdx.y * 128, n0 = blockIdx.x * 64;
    const int K = HID_;
    const int ar0 = t >> 2, aq = t & 3;       // A loader (x2 rows)
    const int br0 = t >> 2, bq = t & 3;       // B loader

    uint32_t aS[2] = { smem_u32(Ash[0]), smem_u32(Ash[1]) };
    uint32_t bS[2] = { smem_u32(Bsh[0]), smem_u32(Bsh[1]) };
    float acc[2][4][4] = {};

    const hf* APs[2] = { Ah, Al };
    const int chunks = K >> 5;
    const int NC = 2 * chunks;

    CP16(aS[0] + ar0*80 + aq*16,      APs[0] + (size_t)(m0+ar0)*K + aq*8);
    CP16(aS[0] + (ar0+64)*80 + aq*16, APs[0] + (size_t)(m0+ar0+64)*K + aq*8);
    CP16(bS[0] + br0*80 + bq*16,      Bh + (size_t)(n0+br0)*K + bq*8);
    CPCOMMIT();

    for (int c = 0; c < NC; c++) {
        const int buf = c & 1;
        CPWAIT0();
        __syncthreads();
        if (c + 1 < NC) {
            const int cn = c + 1;
            const int pn = cn / chunks, kn = cn % chunks;
            const int nb = buf ^ 1;
            CP16(aS[nb] + ar0*80 + aq*16,      APs[pn] + (size_t)(m0+ar0)*K + kn*32 + aq*8);
            CP16(aS[nb] + (ar0+64)*80 + aq*16, APs[pn] + (size_t)(m0+ar0+64)*K + kn*32 + aq*8);
            CP16(bS[nb] + br0*80 + bq*16,      Bh + (size_t)(n0+br0)*K + kn*32 + bq*8);
            CPCOMMIT();
        }
#pragma unroll
        for (int kk = 0; kk < 2; kk++) {
            uint32_t af[2][4], bfr[2][4];
#pragma unroll
            for (int mt = 0; mt < 2; mt++) {
                uint32_t ad = aS[buf] + (uint32_t)((wr32 + mt*16 + a_r)*80 + kk*32 + a_c);
                LDMX4(af[mt], ad);
            }
#pragma unroll
            for (int np = 0; np < 2; np++) {
                uint32_t bd = bS[buf] + (uint32_t)((wc32 + np*16 + b_r)*80 + kk*32 + b_c);
                LDMX4(bfr[np], bd);
            }
#pragma unroll
            for (int mt = 0; mt < 2; mt++)
#pragma unroll
                for (int nt = 0; nt < 4; nt++)
                    MMA16816(acc[mt][nt], af[mt], bfr[nt>>1][(nt&1)*2], bfr[nt>>1][(nt&1)*2+1]);
        }
    }

#pragma unroll
    for (int mt = 0; mt < 2; mt++) {
#pragma unroll
        for (int h = 0; h < 2; h++) {
            const int m = m0 + wr32 + mt*16 + g + 8*h;
#pragma unroll
            for (int nt = 0; nt < 4; nt++) {
                const int n = n0 + wc32 + nt*8 + 2*tg;
                float2 r = { acc[mt][nt][h*2], acc[mt][nt][h*2+1] };
                r.x += bias[n]; r.y += bias[n+1];
                const int sect = n >> 8, cc = n & 255;
                if (sect == 0) {
                    __align__(4) hf hh[2] = { __float2half_rn(r.x), __float2half_rn(r.y) };
                    *(uint32_t*)&Qh[(size_t)m*HID_ + cc] = *(uint32_t*)hh;
                } else if (sect == 1) {
                    __align__(4) hf hh[2] = { __float2half_rn(r.x), __float2half_rn(r.y) };
                    *(uint32_t*)&Kh[(size_t)m*HID_ + cc] = *(uint32_t*)hh;
                } else {
                    Vth[(size_t)cc * N_ + m]     = __float2half_rn(r.x);
                    Vth[(size_t)(cc+1) * N_ + m] = __float2half_rn(r.y);
                }
            }
        }
    }
}

// ---- shared mma-core macro (128x128 kernels) ----
#define COMPUTE32(abase, bbase)                                                     \
    _Pragma("unroll")                                                               \
    for (int kk = 0; kk < 2; kk++) {                                                \
        uint32_t af[4][4], bfr[2][4];                                               \
        _Pragma("unroll")                                                           \
        for (int mt = 0; mt < 4; mt++) {                                            \
            uint32_t ad = (abase) + (uint32_t)((wr64 + mt*16 + a_r)*80 + kk*32 + a_c); \
            LDMX4(af[mt], ad);                                                      \
        }                                                                           \
        _Pragma("unroll")                                                           \
        for (int np = 0; np < 2; np++) {                                            \
            uint32_t bd = (bbase) + (uint32_t)((wc32 + np*16 + b_r)*80 + kk*32 + b_c); \
            LDMX4(bfr[np], bd);                                                     \
        }                                                                           \
        _Pragma("unroll")                                                           \
        for (int mt = 0; mt < 4; mt++)                                              \
            _Pragma("unroll")                                                       \
            for (int nt = 0; nt < 4; nt++)                                          \
                MMA16816(acc[mt][nt], af[mt], bfr[nt>>1][(nt&1)*2], bfr[nt>>1][(nt&1)*2+1]); \
    }

// ================= scores via fp16 mma, single pass, cp.async pipeline =================
__global__ __launch_bounds__(256) void scores_mma(
    const hf* __restrict__ qh, const hf* __restrict__ kh,
    const float* __restrict__ xyz,
    const uint32_t* __restrict__ Mb,
    float* __restrict__ S)
{
    __shared__ __align__(16) char Ash[2][128*80];
    __shared__ __align__(16) char Bsh[2][128*80];
    __shared__ float gix[128*3], gisq[128], giy[128];
    __shared__ float gjx[128*3], gjsq[128], gjy[128];
    const int t = threadIdx.x, lane = t & 31, wid = t >> 5;
    const int wr64 = (wid >> 2) * 64, wc32 = (wid & 3) * 32;
    const int g = lane >> 2, tg = lane & 3;
    const int a_r = ((lane >> 3) & 1) * 8 + (lane & 7);
    const int a_c = (lane >> 4) * 16;
    const int b_r = ((lane >> 4) & 1) * 8 + (lane & 7);
    const int b_c = ((lane >> 3) & 1) * 16;
    const int i0 = blockIdx.y * 128, j0 = blockIdx.x * 128;
    const int lrow = t >> 2, lq = t & 3;

    uint32_t aS[2] = { smem_u32(Ash[0]), smem_u32(Ash[1]) };
    uint32_t bS[2] = { smem_u32(Bsh[0]), smem_u32(Bsh[1]) };
    float acc[4][4][4] = {};

    // issue chunk 0
    CP16(aS[0] + lrow*80 + lq*16,      qh + (size_t)(i0+lrow)*HID_ + lq*8);
    CP16(aS[0] + (lrow+64)*80 + lq*16, qh + (size_t)(i0+lrow+64)*HID_ + lq*8);
    CP16(bS[0] + lrow*80 + lq*16,      kh + (size_t)(j0+lrow)*HID_ + lq*8);
    CP16(bS[0] + (lrow+64)*80 + lq*16, kh + (size_t)(j0+lrow+64)*HID_ + lq*8);
    CPCOMMIT();

    if (t < 128) {
        float a = xyz[(i0+t)*3+0], b = xyz[(i0+t)*3+1], c = xyz[(i0+t)*3+2];
        gix[t*3+0]=a; gix[t*3+1]=b; gix[t*3+2]=c;
        gisq[t] = fmaf(c,c,fmaf(b,b,a*a));
        giy[t]  = g_y[i0+t];
    } else {
        int u = t - 128;
        float a = xyz[(j0+u)*3+0], b = xyz[(j0+u)*3+1], c = xyz[(j0+u)*3+2];
        gjx[u*3+0]=a; gjx[u*3+1]=b; gjx[u*3+2]=c;
        gjsq[u] = fmaf(c,c,fmaf(b,b,a*a));
        gjy[u]  = g_y[j0+u];
    }

    const int NC = 8;
    for (int c = 0; c < NC; c++) {
        const int buf = c & 1;
        CPWAIT0();
        __syncthreads();
        if (c + 1 < NC) {
            const int kc = c + 1;
            const int nb = buf ^ 1;
            CP16(aS[nb] + lrow*80 + lq*16,      qh + (size_t)(i0+lrow)*HID_ + kc*32 + lq*8);
            CP16(aS[nb] + (lrow+64)*80 + lq*16, qh + (size_t)(i0+lrow+64)*HID_ + kc*32 + lq*8);
            CP16(bS[nb] + lrow*80 + lq*16,      kh + (size_t)(j0+lrow)*HID_ + kc*32 + lq*8);
            CP16(bS[nb] + (lrow+64)*80 + lq*16, kh + (size_t)(j0+lrow+64)*HID_ + kc*32 + lq*8);
            CPCOMMIT();
        }
        COMPUTE32(aS[buf], bS[buf]);
    }

#pragma unroll
    for (int mt = 0; mt < 4; mt++) {
#pragma unroll
        for (int h = 0; h < 2; h++) {
            const int li = wr64 + mt*16 + g + 8*h;
            const int gi = i0 + li;
            const float xa = gix[li*3], xbv = gix[li*3+1], xc = gix[li*3+2];
            const float sqa = gisq[li], ya = giy[li];
            const size_t rb = (size_t)gi * N_;
            const uint32_t wbits = Mb[(size_t)gi * (N_/32) + ((j0 + wc32) >> 5)];
#pragma unroll
            for (int nt = 0; nt < 4; nt++) {
                const int lj0 = wc32 + nt*8 + 2*tg;
                float2 r;
#pragma unroll
                for (int e = 0; e < 2; e++) {
                    const int lj = lj0 + e;
                    const int bitpos = nt*8 + 2*tg + e;
                    float dot = fmaf(xc, gjx[lj*3+2], fmaf(xbv, gjx[lj*3+1], xa * gjx[lj*3]));
                    float dist2 = (sqa + gjsq[lj]) - 2.0f * dot;
                    bool ok = ((wbits >> bitpos) & 1u) && (dist2 <= 100.0f);
                    float av = acc[mt][nt][h*2 + e];
                    ((float*)&r)[e] = ok ? (av * 0.0625f - fabsf(ya - gjy[lj])) : NEG_;
                }
                *(float2*)&S[rb + j0 + lj0] = r;
            }
        }
    }
}

// ================= attn@V via fp16 mma, single-pass, split-K z, cp.async ======
__global__ __launch_bounds__(256) void attnv_mma(
    const hf* __restrict__ Sh,
    const hf* __restrict__ Vth,
    float* __restrict__ Cpart)
{
    __shared__ __align__(16) char Ash[2][128*80];
    __shared__ __align__(16) char Bsh[2][128*80];
    const int t = threadIdx.x, lane = t & 31, wid = t >> 5;
    const int wr64 = (wid >> 2) * 64, wc32 = (wid & 3) * 32;
    const int g = lane >> 2, tg = lane & 3;
    const int a_r = ((lane >> 3) & 1) * 8 + (lane & 7);
    const int a_c = (lane >> 4) * 16;
    const int b_r = ((lane >> 4) & 1) * 8 + (lane & 7);
    const int b_c = ((lane >> 3) & 1) * 16;
    const int m0 = blockIdx.y * 128, n0 = blockIdx.x * 128;
    const int kbase = blockIdx.z * (N_ / KZ_);
    const int lrow = t >> 2, lq = t & 3;

    uint32_t aS[2] = { smem_u32(Ash[0]), smem_u32(Ash[1]) };
    uint32_t bS[2] = { smem_u32(Bsh[0]), smem_u32(Bsh[1]) };
    float acc[4][4][4] = {};

    const int NC = (N_ / KZ_) / 32;

    CP16(aS[0] + lrow*80 + lq*16,      Sh + (size_t)(m0+lrow)*N_ + kbase + lq*8);
    CP16(aS[0] + (lrow+64)*80 + lq*16, Sh + (size_t)(m0+lrow+64)*N_ + kbase + lq*8);
    CP16(bS[0] + lrow*80 + lq*16,      Vth + (size_t)(n0+lrow)*N_ + kbase + lq*8);
    CP16(bS[0] + (lrow+64)*80 + lq*16, Vth + (size_t)(n0+lrow+64)*N_ + kbase + lq*8);
    CPCOMMIT();

    for (int c = 0; c < NC; c++) {
        const int buf = c & 1;
        CPWAIT0();
        __syncthreads();
        if (c + 1 < NC) {
            const int kc = c + 1;
            const int nb = buf ^ 1;
            CP16(aS[nb] + lrow*80 + lq*16,      Sh + (size_t)(m0+lrow)*N_ + kbase + kc*32 + lq*8);
            CP16(aS[nb] + (lrow+64)*80 + lq*16, Sh + (size_t)(m0+lrow+64)*N_ + kbase + kc*32 + lq*8);
            CP16(bS[nb] + lrow*80 + lq*16,      Vth + (size_t)(n0+lrow)*N_ + kbase + kc*32 + lq*8);
            CP16(bS[nb] + (lrow+64)*80 + lq*16, Vth + (size_t)(n0+lrow+64)*N_ + kbase + kc*32 + lq*8);
            CPCOMMIT();
        }
        COMPUTE32(aS[buf], bS[buf]);
    }

    float* Cz = Cpart + (size_t)blockIdx.z * N_ * HID_;
#pragma unroll
    for (int mt = 0; mt < 4; mt++) {
#pragma unroll
        for (int h = 0; h < 2; h++) {
            const int m = m0 + wr64 + mt*16 + g + 8*h;
            const size_t rb = (size_t)m * HID_;
#pragma unroll
            for (int nt = 0; nt < 4; nt++) {
                const int n = n0 + wc32 + nt*8 + 2*tg;
                float2 r = { acc[mt][nt][h*2], acc[mt][nt][h*2 + 1] };
                *(float2*)&Cz[rb + n] = r;
            }
        }
    }
}

__global__ void combine_parts(const float* __restrict__ P,
                              hf* __restrict__ Hh, hf* __restrict__ Hl)
{
    int i = blockIdx.x * blockDim.x + threadIdx.x;
    const size_t n = (size_t)N_ * HID_;
    float4 a = *(const float4*)&P[(size_t)i*4];
    float4 b = *(const float4*)&P[n + (size_t)i*4];
    float4 c = *(const float4*)&P[2*n + (size_t)i*4];
    float4 d = *(const float4*)&P[3*n + (size_t)i*4];
    float rv[4] = { a.x+b.x+c.x+d.x, a.y+b.y+c.y+d.y, a.z+b.z+c.z+d.z, a.w+b.w+c.w+d.w };
    __align__(8) hf hh[4], ll[4];
#pragma unroll
    for (int e = 0; e < 4; e++) split1h(rv[e], hh[e], ll[e]);
    *(uint2*)&Hh[(size_t)i*4] = *(uint2*)hh;
    *(uint2*)&Hl[(size_t)i*4] = *(uint2*)ll;
}

// ---------------- softmax + attn@xyz + fp16 store (shuffle reductions) ----------------
__global__ void softmax_xyz(const float* __restrict__ S,
                            hf* __restrict__ Sh,
                            const float* __restrict__ xs, const float* __restrict__ ys,
                            const float* __restrict__ zs, float* __restrict__ out)
{
    __shared__ float red[8];
    __shared__ float r3[24];
    const int row = blockIdx.x, t = threadIdx.x, lane = t & 31, wid = t >> 5;
    const float* p = S + (size_t)row * N_;
    float4 v[4];
    float mx = -1e30f;
#pragma unroll
    for (int c = 0; c < 4; c++) {
        v[c] = *(const float4*)&p[c*1024 + t*4];
        mx = fmaxf(mx, fmaxf(fmaxf(v[c].x, v[c].y), fmaxf(v[c].z, v[c].w)));
    }
#pragma unroll
    for (int o = 16; o > 0; o >>= 1) mx = fmaxf(mx, __shfl_xor_sync(0xffffffffu, mx, o));
    if (lane == 0) red[wid] = mx;
    __syncthreads();
    mx = red[0];
#pragma unroll
    for (int w = 1; w < 8; w++) mx = fmaxf(mx, red[w]);
    __syncthreads();

    float sum = 0.0f;
#pragma unroll
    for (int c = 0; c < 4; c++) {
        v[c].x = fast_exp(v[c].x - mx); v[c].y = fast_exp(v[c].y - mx);
        v[c].z = fast_exp(v[c].z - mx); v[c].w = fast_exp(v[c].w - mx);
        sum += v[c].x + v[c].y + v[c].z + v[c].w;
    }
#pragma unroll
    for (int o = 16; o > 0; o >>= 1) sum += __shfl_xor_sync(0xffffffffu, sum, o);
    if (lane == 0) red[wid] = sum;
    __syncthreads();
    sum = red[0];
#pragma unroll
    for (int w = 1; w < 8; w++) sum += red[w];
    const float inv = 1.0f / sum;

    float a0 = 0.f, a1 = 0.f, a2 = 0.f;
#pragma unroll
    for (int c = 0; c < 4; c++) {
        v[c].x *= inv; v[c].y *= inv; v[c].z *= inv; v[c].w *= inv;
        float vv[4] = { v[c].x, v[c].y, v[c].z, v[c].w };
        __align__(8) hf vh[4];
#pragma unroll
        for (int e = 0; e < 4; e++) vh[e] = __float2half_rn(vv[e]);
        const size_t off = (size_t)row * N_ + c*1024 + t*4;
        *(uint2*)&Sh[off] = *(uint2*)vh;
        const int j = c*1024 + t*4;
        a0 = fmaf(v[c].x, xs[j], fmaf(v[c].y, xs[j+1], fmaf(v[c].z, xs[j+2], fmaf(v[c].w, xs[j+3], a0))));
        a1 = fmaf(v[c].x, ys[j], fmaf(v[c].y, ys[j+1], fmaf(v[c].z, ys[j+2], fmaf(v[c].w, ys[j+3], a1))));
        a2 = fmaf(v[c].x, zs[j], fmaf(v[c].y, zs[j+1], fmaf(v[c].z, zs[j+2], fmaf(v[c].w, zs[j+3], a2))));
    }
#pragma unroll
    for (int o = 16; o > 0; o >>= 1) {
        a0 += __shfl_xor_sync(0xffffffffu, a0, o);
        a1 += __shfl_xor_sync(0xffffffffu, a1, o);
        a2 += __shfl_xor_sync(0xffffffffu, a2, o);
    }
    if (lane == 0) { r3[wid*3+0] = a0; r3[wid*3+1] = a1; r3[wid*3+2] = a2; }
    __syncthreads();
    if (t == 0) {
        float s0 = 0.f, s1 = 0.f, s2 = 0.f;
#pragma unroll
        for (int w = 0; w < 8; w++) { s0 += r3[w*3]; s1 += r3[w*3+1]; s2 += r3[w*3+2]; }
        out[row*3+0] = s0; out[row*3+1] = s1; out[row*3+2] = s2;
    }
}

__global__ void xyz2soa(const float* __restrict__ xyz, float* __restrict__ xs,
                        float* __restrict__ ys, float* __restrict__ zs)
{
    int i = blockIdx.x * blockDim.x + threadIdx.x;
    if (i < N_) { xs[i] = xyz[3*i]; ys[i] = xyz[3*i+1]; zs[i] = xyz[3*i+2]; }
}

// ---------------- GAT pieces ----------------
__global__ void compute_elr(const float* __restrict__ hl, const float* __restrict__ al,
                            const float* __restrict__ ar)
{
    int idx = blockIdx.x * blockDim.x + threadIdx.x;
    if (idx >= N_*4) return;
    int node = idx >> 2, h = idx & 3;
    const float* row = hl + (size_t)node * HID_ + h * 64;
    float sl = 0.f, sr = 0.f;
#pragma unroll 8
    for (int d = 0; d < 64; d++) {
        float v = row[d];
        sl = fmaf(v, al[h*64+d], sl);
        sr = fmaf(v, ar[h*64+d], sr);
    }
    g_el[idx] = sl; g_er[idx] = sr;
}

__global__ void zero_cnt() { int i = blockIdx.x*blockDim.x + threadIdx.x; if (i < N_) g_cnt[i] = 0; }
__global__ void count_edges(const int* __restrict__ dst) {
    int e = blockIdx.x*blockDim.x + threadIdx.x; if (e < E_) atomicAdd(&g_cnt[dst[e]], 1);
}
__global__ void scan4096() {
    __shared__ int part[1024];
    int t = threadIdx.x, base = t * 4;
    int a0 = g_cnt[base], a1 = g_cnt[base+1], a2 = g_cnt[base+2], a3 = g_cnt[base+3];
    int s = a0 + a1 + a2 + a3;
    part[t] = s; __syncthreads();
    for (int off = 1; off < 1024; off <<= 1) {
        int v = (t >= off) ? part[t-off] : 0;
        __syncthreads();
        part[t] += v;
        __syncthreads();
    }
    int excl = part[t] - s;
    g_rowptr[base+0] = excl;           g_cur[base+0] = excl;
    g_rowptr[base+1] = excl+a0;        g_cur[base+1] = excl+a0;
    g_rowptr[base+2] = excl+a0+a1;     g_cur[base+2] = excl+a0+a1;
    g_rowptr[base+3] = excl+a0+a1+a2;  g_cur[base+3] = excl+a0+a1+a2;
    if (t == 1023) g_rowptr[4096] = part[1023];
}
__global__ void scatter_edges(const int* __restrict__ src, const int* __restrict__ dst) {
    int e = blockIdx.x*blockDim.x + threadIdx.x;
    if (e < E_) { int p = atomicAdd(&g_cur[dst[e]], 1); g_psrc[p] = src[e]; }
}

__global__ void gat_aggregate(const float* __restrict__ hl, float* __restrict__ xg)
{
    const int node = (blockIdx.x * blockDim.x + threadIdx.x) >> 5;
    const int lane = threadIdx.x & 31;
    if (node >= N_) return;
    const int beg = g_rowptr[node], end = g_rowptr[node+1];
    const float er_i = (lane < 4) ? g_er[node*4 + lane] : 0.f;
    float m = -1e30f;
    for (int p = beg; p < end; p++) {
        int s = g_psrc[p];
        if (lane < 4) {
            float v = g_el[s*4 + lane] + er_i;
            float e = (v > 0.f) ? v : 0.2f * v;
            m = fmaxf(m, e);
        }
    }
    float m0 = __shfl_sync(0xffffffffu, m, 0), m1 = __shfl_sync(0xffffffffu, m, 1);
    float m2 = __shfl_sync(0xffffffffu, m, 2), m3 = __shfl_sync(0xffffffffu, m, 3);
    const int myh = lane >> 3;
    float4 acc0 = {0,0,0,0}, acc1 = {0,0,0,0};
    float z = 0.f;
    for (int p = beg; p < end; p++) {
        int s = g_psrc[p];
        float w = 0.f;
        if (lane < 4) {
            float v = g_el[s*4 + lane] + er_i;
            float e = (v > 0.f) ? v : 0.2f * v;
            float mm = (lane==0)?m0:(lane==1)?m1:(lane==2)?m2:m3;
            w = fast_exp(e - mm);
            z += w;
        }
        float w0 = __shfl_sync(0xffffffffu, w, 0), w1 = __shfl_sync(0xffffffffu, w, 1);
        float w2 = __shfl_sync(0xffffffffu, w, 2), w3 = __shfl_sync(0xffffffffu, w, 3);
        float wm = (myh==0)?w0:(myh==1)?w1:(myh==2)?w2:w3;
        const float4* hp = (const float4*)(hl + (size_t)s * HID_ + lane * 8);
        float4 hv0 = hp[0], hv1 = hp[1];
        acc0.x=fmaf(wm,hv0.x,acc0.x); acc0.y=fmaf(wm,hv0.y,acc0.y);
        acc0.z=fmaf(wm,hv0.z,acc0.z); acc0.w=fmaf(wm,hv0.w,acc0.w);
        acc1.x=fmaf(wm,hv1.x,acc1.x); acc1.y=fmaf(wm,hv1.y,acc1.y);
        acc1.z=fmaf(wm,hv1.z,acc1.z); acc1.w=fmaf(wm,hv1.w,acc1.w);
    }
    float z0 = __shfl_sync(0xffffffffu, z, 0), z1 = __shfl_sync(0xffffffffu, z, 1);
    float z2 = __shfl_sync(0xffffffffu, z, 2), z3 = __shfl_sync(0xffffffffu, z, 3);
    float zm = (myh==0)?z0:(myh==1)?z1:(myh==2)?z2:z3;
    float inv = 1.0f / (zm + 1e-9f);
    acc0.x*=inv; acc0.y*=inv; acc0.z*=inv; acc0.w*=inv;
    acc1.x*=inv; acc1.y*=inv; acc1.z*=inv; acc1.w*=inv;
    float4* op = (float4*)(xg + (size_t)node * HID_ + lane * 8);
    op[0] = acc0; op[1] = acc1;
}

__global__ void pack_support(const float* __restrict__ xg, const float* __restrict__ h0,
                             hf* __restrict__ suph, hf* __restrict__ supl)
{
    int i = blockIdx.x * blockDim.x + threadIdx.x;
    if (i >= N_ * 512) return;
    int r = i >> 9, c = i & 511;
    float v = (c < 256) ? xg[(size_t)r*256 + c] : h0[(size_t)r*256 + (c-256)];
    hf h, l; split1h(v, h, l);
    suph[i] = h; supl[i] = l;
}

__global__ void yhat_k(const float* __restrict__ x, const float* __restrict__ W,
                       const float* __restrict__ b)
{
    int i = blockIdx.x * blockDim.x + threadIdx.x;
    if (i >= N_) return;
    const float* r = x + (size_t)i * HID_;
    float l0 = b[0], l1 = b[1];
#pragma unroll 8
    for (int d = 0; d < HID_; d++) {
        float v = r[d];
        l0 = fmaf(v, W[2*d+0], l0);
        l1 = fmaf(v, W[2*d+1], l1);
    }
    g_y[i] = 1.0f / (1.0f + expf(l0 - l1));
}

__global__ void cls_k(const float* __restrict__ x, const float* __restrict__ W,
                      const float* __restrict__ b, float* __restrict__ out)
{
    int i = blockIdx.x * blockDim.x + threadIdx.x;
    if (i >= N_) return;
    const float* r = x + (size_t)i * HID_;
    float l0 = b[0], l1 = b[1];
#pragma unroll 8
    for (int d = 0; d < HID_; d++) {
        float v = r[d];
        l0 = fmaf(v, W[2*d+0], l0);
        l1 = fmaf(v, W[2*d+1], l1);
    }
    out[2*i+0] = l0;
    out[2*i+1] = l1;
}

// ---------------- host orchestration ----------------
extern "C" void kernel_launch(void* const* d_in, const int* in_sizes, int n_in,
                              void* d_out, int out_size)
{
    const float* feat   = (const float*)d_in[0];
    const float* xyz_in = (const float*)d_in[1];
    const int*   src    = (const int*)  d_in[2];
    const int*   dst    = (const int*)  d_in[3];
    const void*  dmask  = d_in[4];
    const void*  bmask  = d_in[5];
    const float* fcW  = (const float*)d_in[6];
    const float* fcb  = (const float*)d_in[7];
    const float* gatW = (const float*)d_in[8];
    const float* al   = (const float*)d_in[9];
    const float* ar   = (const float*)d_in[10];
    const float* gcW  = (const float*)d_in[11];
    const float* cgW  = (const float*)d_in[12];
    const float* cgb  = (const float*)d_in[13];
    const float* qW   = (const float*)d_in[14];
    const float* qb_  = (const float*)d_in[15];
    const float* kW   = (const float*)d_in[16];
    const float* kb_  = (const float*)d_in[17];
    const float* vW   = (const float*)d_in[18];
    const float* vb_  = (const float*)d_in[19];
    const float* oW   = (const float*)d_in[20];
    const float* ob   = (const float*)d_in[21];
    const float* clsW = (const float*)d_in[22];
    const float* clsb = (const float*)d_in[23];

    float *px, *ph0, *phl, *pxg, *pS, *pxyz0, *pxyz1, *pxs, *pys, *pzs, *ppart, *pqkvb;
    uint32_t *pmb;
    hf *pxh, *pxl, *pfeath, *pfeatl, *psuph, *psupl, *phmsh, *phmsl;
    hf *pqh, *pkh, *pvth, *psh;
    hf *pfcWth, *pgatWth, *pgcWth, *pqkvWth, *poWth;
    cudaGetSymbolAddress((void**)&px,    g_x);
    cudaGetSymbolAddress((void**)&ph0,   g_h0);
    cudaGetSymbolAddress((void**)&phl,   g_hl_);
    cudaGetSymbolAddress((void**)&pxg,   g_xg);
    cudaGetSymbolAddress((void**)&pS,    g_S);
    cudaGetSymbolAddress((void**)&pmb,   g_mb);
    cudaGetSymbolAddress((void**)&pxyz0, g_xyz0);
    cudaGetSymbolAddress((void**)&pxyz1, g_xyz1);
    cudaGetSymbolAddress((void**)&pxs,   g_xs_);
    cudaGetSymbolAddress((void**)&pys,   g_ys_);
    cudaGetSymbolAddress((void**)&pzs,   g_zs_);
    cudaGetSymbolAddress((void**)&ppart, g_part);
    cudaGetSymbolAddress((void**)&pqkvb, g_qkvb);
    cudaGetSymbolAddress((void**)&pxh,   g_xh);
    cudaGetSymbolAddress((void**)&pxl,   g_xl);
    cudaGetSymbolAddress((void**)&pfeath,g_feath);
    cudaGetSymbolAddress((void**)&pfeatl,g_featl);
    cudaGetSymbolAddress((void**)&psuph, g_suph);
    cudaGetSymbolAddress((void**)&psupl, g_supl);
    cudaGetSymbolAddress((void**)&phmsh, g_hmsh);
    cudaGetSymbolAddress((void**)&phmsl, g_hmsl);
    cudaGetSymbolAddress((void**)&pqh,   g_qh);
    cudaGetSymbolAddress((void**)&pkh,   g_kh);
    cudaGetSymbolAddress((void**)&pvth,  g_vth);
    cudaGetSymbolAddress((void**)&psh,   g_sh);
    cudaGetSymbolAddress((void**)&pfcWth,  g_fcWth);
    cudaGetSymbolAddress((void**)&pgatWth, g_gatWth);
    cudaGetSymbolAddress((void**)&pgcWth,  g_gcWth);
    cudaGetSymbolAddress((void**)&pqkvWth, g_qkvWth);
    cudaGetSymbolAddress((void**)&poWth,   g_oWth);

    detect_mask_mode<<<1, 1>>>((const unsigned int*)dmask);
    maskpack<<<(N_*(N_/32))/256, 256>>>(dmask, bmask, pmb);

    wsplit_t<<<dim3(HID_/32, FEAT_/32, 1), 256>>>(fcW, pfcWth, FEAT_, HID_);
    wsplit_t<<<dim3(HID_/32, HID_/32, 4), 256>>>(gatW, pgatWth, HID_, HID_);
    wsplit_t<<<dim3(HID_/32, 2*HID_/32, 4), 256>>>(gcW, pgcWth, 2*HID_, HID_);
    wsplit_t<<<dim3(HID_/32, HID_/32, 4), 256>>>(oW, poWth, HID_, HID_);
    wsplit_ro_t<<<dim3(8, 8, 4), 256>>>(qW, pqkvWth, 0);
    wsplit_ro_t<<<dim3(8, 8, 4), 256>>>(kW, pqkvWth, 256);
    wsplit_ro_t<<<dim3(8, 8, 4), 256>>>(vW, pqkvWth, 512);
    qkvbias<<<12, 256>>>(qb_, kb_, vb_, pqkvb);
    split_hf<<<(N_*FEAT_/4)/256, 256>>>(feat, pfeath, pfeatl);

    gemm_tc64<<<dim3(HID_/64, N_/64), 256>>>(pfeath, pfeatl, pfcWth, FEAT_, HID_,
                                             fcb, 1, 1.0f, nullptr,0.f, nullptr,0.f, nullptr,0.f,
                                             px, ph0, pxh, pxl);

    zero_cnt<<<N_/256, 256>>>();
    count_edges<<<E_/256, 256>>>(dst);
    scan4096<<<1, 1024>>>();
    scatter_edges<<<E_/256, 256>>>(src, dst);

    const float ALPHA = 0.1f, LAMDA = 0.5f;
    for (int l = 0; l < 4; l++) {
        gemm_tc64<<<dim3(HID_/64, N_/64), 256>>>(pxh, pxl, pgatWth + (size_t)l*HID_*HID_,
                                                 HID_, HID_,
                                                 nullptr, 0, 1.0f, nullptr,0.f, nullptr,0.f, nullptr,0.f,
                                                 phl, nullptr, nullptr, nullptr);
        compute_elr<<<(N_*4)/256, 256>>>(phl, al + l*4*64, ar + l*4*64);
        gat_aggregate<<<N_/8, 256>>>(phl, pxg);
        pack_support<<<(N_*512)/256, 256>>>(pxg, ph0, psuph, psupl);
        float theta = fminf(1.0f, logf(LAMDA / (float)(l + 1) + 1.0f));
        gemm_tc64<<<dim3(HID_/64, N_/64), 256>>>(psuph, psupl, pgcWth + (size_t)l*2*HID_*HID_,
                                                 2*HID_, HID_,
                                                 nullptr, 0, theta,
                                                 pxg, (1.0f-theta)*(1.0f-ALPHA),
                                                 ph0, (1.0f-theta)*ALPHA,
                                                 px,  1.0f,
                                                 px, nullptr, pxh, pxl);
    }

    yhat_k<<<N_/256, 256>>>(px, cgW, cgb);

    const float* xyz_cur = xyz_in;
    float* xyz_buf[2] = { pxyz0, pxyz1 };
    for (int l = 0; l < 4; l++) {
        qkv_tc<<<dim3(768/64, N_/128), 256>>>(pxh, pxl,
                                              pqkvWth + (size_t)l*768*HID_,
                                              pqkvb + l*768,
                                              pqh, pkh, pvth);
        scores_mma<<<dim3(N_/128, N_/128), 256>>>(pqh, pkh, xyz_cur, pmb, pS);
        xyz2soa<<<N_/256, 256>>>(xyz_cur, pxs, pys, pzs);
        softmax_xyz<<<N_, 256>>>(pS, psh, pxs, pys, pzs, xyz_buf[l & 1]);
        attnv_mma<<<dim3(HID_/128, N_/128, KZ_), 256>>>(psh, pvth, ppart);
        combine_parts<<<(N_*HID_/4)/256, 256>>>(ppart, phmsh, phmsl);
        gemm_tc64<<<dim3(HID_/64, N_/64), 256>>>(phmsh, phmsl, poWth + (size_t)l*HID_*HID_,
                                                 HID_, HID_,
                                                 ob + l*HID_, 0, 1.0f,
                                                 px, 1.0f, nullptr,0.f, nullptr,0.f,
                                                 px, nullptr, pxh, pxl);
        xyz_cur = xyz_buf[l & 1];
    }

    cls_k<<<N_/256, 256>>>(px, clsW, clsb, (float*)d_out);
}